// round 11
// baseline (speedup 1.0000x reference)
#include <cuda_runtime.h>
#include <cuda_fp16.h>
#include <cstdint>

// ---------------- problem constants ----------------
#define NSRC0 60000
#define MPAD  60032    // 469 * 128
#define NDST0 15000
#define NDST1 4000
#define NH1   8
#define ND1   256
#define ND2   128
#define HD1   2048   // NH1*ND1 (also IN_DIM)
#define E0MAX 240000
#define E1MAX 64000

// ---------------- device scratch (static, allowed) ----------------
__device__ __half g_Ah[(size_t)MPAD * HD1];          // 246 MB (fp16 feat)
__device__ __half g_Bh[(size_t)HD1 * HD1];           // 8.4 MB (transposed W1: [N,K], fp16)
__device__ __half g_h1[(size_t)NSRC0 * HD1];         // 246 MB (fp16 h1)
__device__ float g_el1[NSRC0 * NH1];
__device__ float g_er1[NDST0 * NH1];
__device__ int   g_off1[NDST0 + 1];
__device__ int   g_cnt1[NDST0];
__device__ int   g_esrc1[E0MAX];
__device__ float g_hm[(size_t)NDST0 * ND1];
__device__ float g_h2[(size_t)NDST0 * ND2];
__device__ float g_el2[NDST0];
__device__ float g_er2[NDST1];
__device__ int   g_off2[NDST1 + 1];
__device__ int   g_cnt2[NDST1];
__device__ int   g_esrc2[E1MAX];

// =====================================================================
// mma.sync fp16 GEMM: C[M,2048] = A @ B^T (fp16 out).  Bt is [N,K].
// CTA tile 128x256, 8 warps as 2(M)x4(N), warp tile 64x64, BK=64,
// 3-stage cp.async (144KB smem, 1 CTA/SM).  Per k-step: 8 LDSM + 32 HMMA
// (80% mma issue fraction vs 73% for the 32x64 warp tile).
// Fused epilogue: el/er attention-score partials via atomicAdd.
// =====================================================================
static __device__ __forceinline__ void cp16(uint32_t s, const void* g) {
    asm volatile("cp.async.cg.shared.global [%0], [%1], 16;" :: "r"(s), "l"(g));
}
static __device__ __forceinline__ void ldsm4(uint32_t* r, uint32_t addr) {
    asm volatile("ldmatrix.sync.aligned.m8n8.x4.shared.b16 {%0,%1,%2,%3}, [%4];"
                 : "=r"(r[0]), "=r"(r[1]), "=r"(r[2]), "=r"(r[3]) : "r"(addr));
}
static __device__ __forceinline__ void mma16816(float* d, const uint32_t* a, const uint32_t* b) {
    asm volatile(
        "mma.sync.aligned.m16n8k16.row.col.f32.f16.f16.f32 "
        "{%0,%1,%2,%3}, {%4,%5,%6,%7}, {%8,%9}, {%0,%1,%2,%3};"
        : "+f"(d[0]), "+f"(d[1]), "+f"(d[2]), "+f"(d[3])
        : "r"(a[0]), "r"(a[1]), "r"(a[2]), "r"(a[3]), "r"(b[0]), "r"(b[1]));
}

#define GBM 128
#define GBN 256
#define GBK 64
#define KCH (HD1 / GBK)        // 32
#define STG 49152              // A 16KB + B 32KB per stage (rows x 128B)
#define NSTAGE 3

__global__ __launch_bounds__(256) void gemm_mma(
    const __half* __restrict__ Ah, const __half* __restrict__ Bh,
    __half* __restrict__ C, int M,
    const float* __restrict__ al1, const float* __restrict__ ar1,
    float* __restrict__ el, float* __restrict__ er)
{
    extern __shared__ __align__(128) char smem[];
    uint32_t sbase = (uint32_t)__cvta_generic_to_shared(smem);

    int tid = threadIdx.x, wid = tid >> 5, lane = tid & 31;
    int mrow = blockIdx.y * GBM;
    int ncol = blockIdx.x * GBN;
    int wm = (wid & 1) * 64;       // warp row base in tile (2 warps in M)
    int wn = (wid >> 1) * 64;      // warp col base in tile (4 warps in N)

    float acc[4][8][4];
#pragma unroll
    for (int i = 0; i < 4; i++)
#pragma unroll
        for (int j = 0; j < 8; j++)
#pragma unroll
            for (int q = 0; q < 4; q++) acc[i][j][q] = 0.f;

    auto stage_load = [&](int it, int s) {
        uint32_t st = sbase + (uint32_t)s * STG;
        int kb = it * GBK;
        // A tile: 128 rows x 64 fp16 = 1024 x 16B chunks
#pragma unroll
        for (int u = 0; u < 4; u++) {
            int idx = tid + u * 256;
            int r = idx >> 3, c = idx & 7;
            uint32_t so = ((uint32_t)r << 7) | ((uint32_t)((c ^ (r & 7))) << 4);
            cp16(st + so, Ah + (size_t)(mrow + r) * HD1 + kb + c * 8);
        }
        // B tile: 256 rows x 64 fp16 = 2048 x 16B chunks
#pragma unroll
        for (int u = 0; u < 8; u++) {
            int idx = tid + u * 256;
            int r = idx >> 3, c = idx & 7;
            uint32_t so = ((uint32_t)r << 7) | ((uint32_t)((c ^ (r & 7))) << 4);
            cp16(st + 16384u + so, Bh + (size_t)(ncol + r) * HD1 + kb + c * 8);
        }
        asm volatile("cp.async.commit_group;");
    };

    auto compute = [&](int s) {
        uint32_t sA = sbase + (uint32_t)s * STG;
        uint32_t sB = sA + 16384u;
#pragma unroll
        for (int ks = 0; ks < 4; ks++) {
            uint32_t a[4][4];
#pragma unroll
            for (int mr = 0; mr < 4; mr++) {
                int row = wm + mr * 16 + (lane & 15);
                int ch = ks * 2 + (lane >> 4);
                ldsm4(a[mr], sA + ((uint32_t)row << 7) + ((uint32_t)((ch ^ (row & 7))) << 4));
            }
            uint32_t b[4][4];
#pragma unroll
            for (int nb = 0; nb < 4; nb++) {
                int n = wn + nb * 16 + (lane & 7) + ((lane >> 4) << 3);
                int ch = ks * 2 + ((lane >> 3) & 1);
                ldsm4(b[nb], sB + ((uint32_t)n << 7) + ((uint32_t)((ch ^ (n & 7))) << 4));
            }
#pragma unroll
            for (int mr = 0; mr < 4; mr++)
#pragma unroll
                for (int nb = 0; nb < 4; nb++)
#pragma unroll
                    for (int hf = 0; hf < 2; hf++)
                        mma16816(acc[mr][nb * 2 + hf], a[mr], &b[nb][hf * 2]);
        }
    };

    stage_load(0, 0);
    stage_load(1, 1);
    for (int it = 0; it < KCH; it++) {
        if (it + 2 < KCH) {
            stage_load(it + 2, (it + 2) % NSTAGE);
            asm volatile("cp.async.wait_group 2;" ::: "memory");
        } else if (it + 1 < KCH) {
            asm volatile("cp.async.wait_group 1;" ::: "memory");
        } else {
            asm volatile("cp.async.wait_group 0;" ::: "memory");
        }
        __syncthreads();
        compute(it % NSTAGE);
        __syncthreads();
    }

    // ---- store C (fp16) ----
#pragma unroll
    for (int mr = 0; mr < 4; mr++)
#pragma unroll
        for (int n8 = 0; n8 < 8; n8++) {
            int row = mrow + wm + mr * 16 + (lane >> 2);
            int col = ncol + wn + n8 * 8 + (lane & 3) * 2;
            float* d = acc[mr][n8];
            if (row < M)
                *(__half2*)(C + (size_t)row * HD1 + col) = __floats2half2_rn(d[0], d[1]);
            if (row + 8 < M)
                *(__half2*)(C + (size_t)(row + 8) * HD1 + col) = __floats2half2_rn(d[2], d[3]);
        }

    // ---- fused attention-score partials: el[n,h] += h.al, er[n,h] += h.ar ----
    {
        int h = ncol >> 8;                       // head index (GBN==ND1: one head/CTA)
        int cb0 = wn + (lane & 3) * 2;           // within-head col of d[0]
        float2 alv[8], arv[8];
        bool wanter = (mrow < NDST0);
#pragma unroll
        for (int n8 = 0; n8 < 8; n8++) {
            int cc = h * ND1 + cb0 + n8 * 8;
            alv[n8] = make_float2(__ldg(al1 + cc), __ldg(al1 + cc + 1));
            if (wanter) arv[n8] = make_float2(__ldg(ar1 + cc), __ldg(ar1 + cc + 1));
        }
        float pe[8] = {0.f, 0.f, 0.f, 0.f, 0.f, 0.f, 0.f, 0.f};
        float pr[8] = {0.f, 0.f, 0.f, 0.f, 0.f, 0.f, 0.f, 0.f};
#pragma unroll
        for (int mr = 0; mr < 4; mr++)
#pragma unroll
            for (int n8 = 0; n8 < 8; n8++) {
                float* d = acc[mr][n8];
                pe[mr * 2 + 0] += d[0] * alv[n8].x + d[1] * alv[n8].y;
                pe[mr * 2 + 1] += d[2] * alv[n8].x + d[3] * alv[n8].y;
                if (wanter) {
                    pr[mr * 2 + 0] += d[0] * arv[n8].x + d[1] * arv[n8].y;
                    pr[mr * 2 + 1] += d[2] * arv[n8].x + d[3] * arv[n8].y;
                }
            }
#pragma unroll
        for (int q = 0; q < 8; q++) {
            pe[q] += __shfl_xor_sync(0xffffffffu, pe[q], 1);
            pe[q] += __shfl_xor_sync(0xffffffffu, pe[q], 2);
            pr[q] += __shfl_xor_sync(0xffffffffu, pr[q], 1);
            pr[q] += __shfl_xor_sync(0xffffffffu, pr[q], 2);
        }
        if ((lane & 3) == 0) {
            int rbase = mrow + wm + (lane >> 2);
#pragma unroll
            for (int q = 0; q < 8; q++) {
                int r = rbase + (q >> 1) * 16 + (q & 1) * 8;
                if (r < NSRC0) atomicAdd(&el[r * NH1 + h], pe[q]);
                if (wanter && r < NDST0) atomicAdd(&er[r * NH1 + h], pr[q]);
            }
        }
    }
}

// ---------------- fp32 -> fp16 conversions (vectorized) ----------------
__global__ void convA(const float* __restrict__ f, __half* __restrict__ o)
{
    size_t i = (size_t)blockIdx.x * blockDim.x + threadIdx.x;   // float4 index
    size_t n4 = (size_t)MPAD * HD1 / 4;
    if (i >= n4) return;
    float4 v;
    if (i < (size_t)NSRC0 * HD1 / 4) v = ((const float4*)f)[i];
    else v = make_float4(0.f, 0.f, 0.f, 0.f);
    ((__half2*)o)[2 * i] = __floats2half2_rn(v.x, v.y);
    ((__half2*)o)[2 * i + 1] = __floats2half2_rn(v.z, v.w);
}
// transpose W1 [K,N] -> Bt [N,K] fp16, 32x32 smem tiles (coalesced both sides)
__global__ __launch_bounds__(256) void convB(const float* __restrict__ W, __half* __restrict__ o)
{
    __shared__ float tile[32][33];
    int kb = blockIdx.x * 32, nb = blockIdx.y * 32;
    int tx = threadIdx.x & 31, ty = threadIdx.x >> 5;   // 32 x 8
#pragma unroll
    for (int r = 0; r < 32; r += 8)
        tile[ty + r][tx] = W[(size_t)(kb + ty + r) * HD1 + nb + tx];
    __syncthreads();
#pragma unroll
    for (int r = 0; r < 32; r += 8)
        o[(size_t)(nb + ty + r) * HD1 + kb + tx] = __float2half_rn(tile[tx][ty + r]);
}

// ---------------- SGEMM (layer 2, tiny): C = A @ B, fp32 ----------------
__global__ __launch_bounds__(256) void sgemm128(
    const float* __restrict__ A, const float* __restrict__ B,
    float* __restrict__ C, int M, int N, int K)
{
    const int BM = 128, BN = 128, BK = 8, TM = 8, TN = 8;
    __shared__ float As[BK][BM];
    __shared__ float Bs[BK][BN];

    int tid = threadIdx.x;
    int tx = tid & 15, ty = tid >> 4;
    int rowBase = blockIdx.y * BM, colBase = blockIdx.x * BN;
    int aRow = tid >> 1, aCol = (tid & 1) * 4;
    int bRow = tid >> 5, bCol = (tid & 31) * 4;

    float acc[TM][TN];
#pragma unroll
    for (int i = 0; i < TM; i++)
#pragma unroll
        for (int j = 0; j < TN; j++) acc[i][j] = 0.f;

    for (int kt = 0; kt < K; kt += BK) {
        int gr = rowBase + aRow;
        float4 av = (gr < M) ? *(const float4*)(A + (size_t)gr * K + kt + aCol)
                             : make_float4(0.f, 0.f, 0.f, 0.f);
        As[aCol + 0][aRow] = av.x; As[aCol + 1][aRow] = av.y;
        As[aCol + 2][aRow] = av.z; As[aCol + 3][aRow] = av.w;
        float4 bv = *(const float4*)(B + (size_t)(kt + bRow) * N + colBase + bCol);
        *(float4*)&Bs[bRow][bCol] = bv;
        __syncthreads();
#pragma unroll
        for (int k = 0; k < BK; k++) {
            float ar_[TM], br_[TN];
#pragma unroll
            for (int i = 0; i < TM; i++) ar_[i] = As[k][ty * TM + i];
#pragma unroll
            for (int j = 0; j < TN; j++) br_[j] = Bs[k][tx * TN + j];
#pragma unroll
            for (int i = 0; i < TM; i++)
#pragma unroll
                for (int j = 0; j < TN; j++) acc[i][j] += ar_[i] * br_[j];
        }
        __syncthreads();
    }
#pragma unroll
    for (int i = 0; i < TM; i++) {
        int gr = rowBase + ty * TM + i;
        if (gr < M) {
            float* cp = C + (size_t)gr * N + colBase + tx * TN;
#pragma unroll
            for (int j = 0; j < TN; j += 4)
                *(float4*)(cp + j) = make_float4(acc[i][j], acc[i][j + 1], acc[i][j + 2], acc[i][j + 3]);
        }
    }
}

// ---------------- layer-2 attention scores ----------------
__global__ __launch_bounds__(128) void scores2(
    const float* __restrict__ h2, const float* __restrict__ al,
    const float* __restrict__ ar, float* __restrict__ el, float* __restrict__ er)
{
    int n = blockIdx.x, t = threadIdx.x;
    __shared__ float sred[4];
    float x = h2[(size_t)n * ND2 + t];
    float v = x * al[t];
#pragma unroll
    for (int o = 16; o > 0; o >>= 1) v += __shfl_xor_sync(0xffffffffu, v, o);
    if ((t & 31) == 0) sred[t >> 5] = v;
    __syncthreads();
    if (t == 0) el[n] = sred[0] + sred[1] + sred[2] + sred[3];
    __syncthreads();
    if (n < NDST1) {
        float v2 = x * ar[t];
#pragma unroll
        for (int o = 16; o > 0; o >>= 1) v2 += __shfl_xor_sync(0xffffffffu, v2, o);
        if ((t & 31) == 0) sred[t >> 5] = v2;
        __syncthreads();
        if (t == 0) er[n] = sred[0] + sred[1] + sred[2] + sred[3];
    }
}

// ---------------- CSR build helpers ----------------
__global__ void count_edges(const int* __restrict__ dst, int ne, int* __restrict__ cnt) {
    int e = blockIdx.x * blockDim.x + threadIdx.x;
    if (e < ne) atomicAdd(&cnt[dst[e]], 1);
}
__global__ __launch_bounds__(1024) void scan_excl(
    const int* __restrict__ cnt, int* __restrict__ off, int n)
{
    __shared__ int s[1024];
    __shared__ int stot;
    int t = threadIdx.x;
    int chunk = (n + 1023) >> 10;
    int b = t * chunk;
    int e = b + chunk; if (e > n) e = n;
    int loc = 0;
    for (int i = b; i < e; i++) loc += cnt[i];
    s[t] = loc;
    __syncthreads();
    if (t == 0) {
        int run = 0;
        for (int i = 0; i < 1024; i++) { int x = s[i]; s[i] = run; run += x; }
        stot = run;
    }
    __syncthreads();
    int run = s[t];
    for (int i = b; i < e; i++) { off[i] = run; run += cnt[i]; }
    if (t == 0) off[n] = stot;
}
__global__ void scatter_edges(const int* __restrict__ src, const int* __restrict__ dst,
                              int ne, const int* __restrict__ off,
                              int* __restrict__ cur, int* __restrict__ esrc) {
    int e = blockIdx.x * blockDim.x + threadIdx.x;
    if (e < ne) {
        int d = dst[e];
        int p = off[d] + atomicAdd(&cur[d], 1);
        esrc[p] = src[e];
    }
}

// ---------------- layer-1 aggregate (shift-free softmax, fp16 gather) ----------------
__global__ __launch_bounds__(256) void aggregate1(
    const __half* __restrict__ h1, const float* __restrict__ el,
    const float* __restrict__ er, const float* __restrict__ b1,
    const int* __restrict__ off, const int* __restrict__ esrc,
    float* __restrict__ hm)
{
    int d = blockIdx.x, t = threadIdx.x;
    __shared__ float s_e[256][NH1];
    __shared__ int   s_src[256];

    int s0 = off[d], s1 = off[d + 1];
    float ssum[NH1], acc[NH1], erh[NH1];
#pragma unroll
    for (int h = 0; h < NH1; h++) {
        ssum[h] = 0.f; acc[h] = 0.f;
        erh[h] = er[d * NH1 + h];
    }

    for (int base = s0; base < s1; base += 256) {
        int cn = s1 - base; if (cn > 256) cn = 256;
        if (t < cn) {
            int s = esrc[base + t];
            s_src[t] = s;
#pragma unroll
            for (int h = 0; h < NH1; h++) {
                float x = el[s * NH1 + h] + erh[h];
                x = (x > 0.f) ? x : 0.2f * x;   // leaky_relu(0.2)
                s_e[t][h] = __expf(x);          // shift-free: |x| small, no overflow
            }
        }
        __syncthreads();

        for (int j = 0; j < cn; j++) {
            const __half* hrow = h1 + (size_t)s_src[j] * HD1 + t;
#pragma unroll
            for (int h = 0; h < NH1; h++) {
                float w = s_e[j][h];
                ssum[h] += w;
                acc[h] += w * __half2float(hrow[h * ND1]);
            }
        }
        __syncthreads();
    }

    float outv = 0.f;
#pragma unroll
    for (int h = 0; h < NH1; h++) {
        float o = (ssum[h] > 0.f) ? acc[h] / ssum[h] : 0.f;
        o += b1[h * ND1 + t];
        o = fmaxf(o, 0.f);       // relu (act=True)
        outv += o;
    }
    hm[(size_t)d * ND1 + t] = outv * 0.125f;   // head mean
}

// ---------------- layer-2 aggregate (shift-free softmax) ----------------
__global__ __launch_bounds__(128) void aggregate2(
    const float* __restrict__ h2, const float* __restrict__ el,
    const float* __restrict__ er, const float* __restrict__ b2,
    const int* __restrict__ off, const int* __restrict__ esrc,
    float* __restrict__ out)
{
    int d = blockIdx.x, t = threadIdx.x;
    __shared__ float s_e[128];
    __shared__ int   s_src[128];

    int s0 = off[d], s1 = off[d + 1];
    float ssum = 0.f, acc = 0.f;
    float erh = er[d];

    for (int base = s0; base < s1; base += 128) {
        int cn = s1 - base; if (cn > 128) cn = 128;
        if (t < cn) {
            int s = esrc[base + t];
            s_src[t] = s;
            float x = el[s] + erh;
            x = (x > 0.f) ? x : 0.2f * x;
            s_e[t] = __expf(x);
        }
        __syncthreads();

        for (int j = 0; j < cn; j++) {
            float w = s_e[j];
            ssum += w;
            acc += w * h2[(size_t)s_src[j] * ND2 + t];
        }
        __syncthreads();
    }

    float o = (ssum > 0.f) ? acc / ssum : 0.f;
    out[(size_t)d * ND2 + t] = o + b2[t];
}

// ---------------- launch ----------------
extern "C" void kernel_launch(void* const* d_in, const int* in_sizes, int n_in,
                              void* d_out, int out_size)
{
    const float* feat = (const float*)d_in[0];
    const float* W1   = (const float*)d_in[1];
    const float* al1  = (const float*)d_in[2];
    const float* ar1  = (const float*)d_in[3];
    const float* b1   = (const float*)d_in[4];
    const float* W2   = (const float*)d_in[5];
    const float* al2  = (const float*)d_in[6];
    const float* ar2  = (const float*)d_in[7];
    const float* b2   = (const float*)d_in[8];
    const int* src0 = (const int*)d_in[9];
    const int* dst0 = (const int*)d_in[10];
    const int* src1 = (const int*)d_in[11];
    const int* dst1 = (const int*)d_in[12];
    float* out = (float*)d_out;

    int e0 = in_sizes[9];
    int e1 = in_sizes[11];

    __half *Ahp, *Bhp, *h1p;
    float *hmp, *h2p, *el1p, *er1p, *el2p, *er2p;
    int *off1p, *cnt1p, *esrc1p, *off2p, *cnt2p, *esrc2p;
    cudaGetSymbolAddress((void**)&Ahp, g_Ah);
    cudaGetSymbolAddress((void**)&Bhp, g_Bh);
    cudaGetSymbolAddress((void**)&h1p, g_h1);
    cudaGetSymbolAddress((void**)&hmp, g_hm);
    cudaGetSymbolAddress((void**)&h2p, g_h2);
    cudaGetSymbolAddress((void**)&el1p, g_el1);
    cudaGetSymbolAddress((void**)&er1p, g_er1);
    cudaGetSymbolAddress((void**)&el2p, g_el2);
    cudaGetSymbolAddress((void**)&er2p, g_er2);
    cudaGetSymbolAddress((void**)&off1p, g_off1);
    cudaGetSymbolAddress((void**)&cnt1p, g_cnt1);
    cudaGetSymbolAddress((void**)&esrc1p, g_esrc1);
    cudaGetSymbolAddress((void**)&off2p, g_off2);
    cudaGetSymbolAddress((void**)&cnt2p, g_cnt2);
    cudaGetSymbolAddress((void**)&esrc2p, g_esrc2);

    // ---- layer 1: fp16 mma.sync GEMM + fused scores ----
    {
        size_t n4 = (size_t)MPAD * HD1 / 4;
        convA<<<(unsigned)((n4 + 255) / 256), 256>>>(feat, Ahp);
        convB<<<dim3(HD1 / 32, HD1 / 32), 256>>>(W1, Bhp);
        cudaMemsetAsync(el1p, 0, (size_t)NSRC0 * NH1 * sizeof(float));
        cudaMemsetAsync(er1p, 0, (size_t)NDST0 * NH1 * sizeof(float));

        const int SMEM_GEMM = NSTAGE * STG;  // 144 KB
        cudaFuncSetAttribute(gemm_mma, cudaFuncAttributeMaxDynamicSharedMemorySize, SMEM_GEMM);
        dim3 grid(HD1 / GBN, MPAD / GBM);   // (8, 469)
        gemm_mma<<<grid, 256, SMEM_GEMM>>>(Ahp, Bhp, h1p, NSRC0,
                                           al1, ar1, el1p, er1p);
    }

    cudaMemsetAsync(cnt1p, 0, NDST0 * sizeof(int));
    count_edges<<<(e0 + 255) / 256, 256>>>(dst0, e0, cnt1p);
    scan_excl<<<1, 1024>>>(cnt1p, off1p, NDST0);
    cudaMemsetAsync(cnt1p, 0, NDST0 * sizeof(int));
    scatter_edges<<<(e0 + 255) / 256, 256>>>(src0, dst0, e0, off1p, cnt1p, esrc1p);

    aggregate1<<<NDST0, 256>>>(h1p, el1p, er1p, b1, off1p, esrc1p, hmp);

    // ---- layer 2 ----
    {
        dim3 grid(ND2 / 128, (NDST0 + 127) / 128);
        sgemm128<<<grid, 256>>>(hmp, W2, h2p, NDST0, ND2, ND1);
    }
    scores2<<<NDST0, 128>>>(h2p, al2, ar2, el2p, er2p);

    cudaMemsetAsync(cnt2p, 0, NDST1 * sizeof(int));
    count_edges<<<(e1 + 255) / 256, 256>>>(dst1, e1, cnt2p);
    scan_excl<<<1, 1024>>>(cnt2p, off2p, NDST1);
    cudaMemsetAsync(cnt2p, 0, NDST1 * sizeof(int));
    scatter_edges<<<(e1 + 255) / 256, 256>>>(src1, dst1, e1, off2p, cnt2p, esrc2p);

    aggregate2<<<NDST1, 128>>>(h2p, el2p, er2p, b2, off2p, esrc2p, out);
}

// round 12
// speedup vs baseline: 1.1073x; 1.1073x over previous
#include <cuda_runtime.h>
#include <cuda_fp16.h>
#include <cstdint>

// ---------------- problem constants ----------------
#define NSRC0 60000
#define MPAD  60032    // 469 * 128
#define NDST0 15000
#define NDST1 4000
#define NH1   8
#define ND1   256
#define ND2   128
#define HD1   2048   // NH1*ND1 (also IN_DIM)
#define E0MAX 240000
#define E1MAX 64000

// ---------------- device scratch (static, allowed) ----------------
__device__ __half g_Ah[(size_t)MPAD * HD1];          // 246 MB (fp16 feat)
__device__ __half g_Bh[(size_t)HD1 * HD1];           // 8.4 MB (transposed W1: [N,K], fp16)
__device__ __half g_h1[(size_t)NSRC0 * HD1];         // 246 MB (fp16 h1)
__device__ float g_el1[NSRC0 * NH1];
__device__ float g_er1[NDST0 * NH1];
__device__ int   g_off1[NDST0 + 1];
__device__ int   g_cnt1[NDST0];
__device__ int   g_esrc1[E0MAX];
__device__ float g_hm[(size_t)NDST0 * ND1];
__device__ float g_h2[(size_t)NDST0 * ND2];
__device__ float g_el2[NDST0];
__device__ float g_er2[NDST1];
__device__ int   g_off2[NDST1 + 1];
__device__ int   g_cnt2[NDST1];
__device__ int   g_esrc2[E1MAX];

// =====================================================================
// mma.sync fp16 GEMM (R9 config — best measured: 1117us, tensor=74%)
// C[M,2048] = A @ B^T (fp16 out).  Bt is [N,K].
// CTA 128x128, BK=64, 3-stage cp.async, 256 threads, warp tile 32x64,
// __launch_bounds__(256,2) -> 128 regs, 2 CTAs/SM (2x96KB smem).
// Fused epilogue: el/er attention-score partials via atomicAdd.
// =====================================================================
static __device__ __forceinline__ void cp16(uint32_t s, const void* g) {
    asm volatile("cp.async.cg.shared.global [%0], [%1], 16;" :: "r"(s), "l"(g));
}
static __device__ __forceinline__ void ldsm4(uint32_t* r, uint32_t addr) {
    asm volatile("ldmatrix.sync.aligned.m8n8.x4.shared.b16 {%0,%1,%2,%3}, [%4];"
                 : "=r"(r[0]), "=r"(r[1]), "=r"(r[2]), "=r"(r[3]) : "r"(addr));
}
static __device__ __forceinline__ void mma16816(float* d, const uint32_t* a, const uint32_t* b) {
    asm volatile(
        "mma.sync.aligned.m16n8k16.row.col.f32.f16.f16.f32 "
        "{%0,%1,%2,%3}, {%4,%5,%6,%7}, {%8,%9}, {%0,%1,%2,%3};"
        : "+f"(d[0]), "+f"(d[1]), "+f"(d[2]), "+f"(d[3])
        : "r"(a[0]), "r"(a[1]), "r"(a[2]), "r"(a[3]), "r"(b[0]), "r"(b[1]));
}

#define GBM 128
#define GBN 128
#define GBK 64
#define KCH (HD1 / GBK)        // 32
#define STG 32768              // A 16KB + B 16KB per stage (128 rows x 128B)
#define NSTAGE 3

__global__ __launch_bounds__(256, 2) void gemm_mma(
    const __half* __restrict__ Ah, const __half* __restrict__ Bh,
    __half* __restrict__ C, int M,
    const float* __restrict__ al1, const float* __restrict__ ar1,
    float* __restrict__ el, float* __restrict__ er)
{
    extern __shared__ __align__(128) char smem[];
    uint32_t sbase = (uint32_t)__cvta_generic_to_shared(smem);

    int tid = threadIdx.x, wid = tid >> 5, lane = tid & 31;
    int mrow = blockIdx.y * GBM;
    int ncol = blockIdx.x * GBN;
    int wm = (wid & 3) * 32;       // warp row base in tile
    int wn = (wid >> 2) * 64;      // warp col base in tile

    float acc[2][8][4];
#pragma unroll
    for (int i = 0; i < 2; i++)
#pragma unroll
        for (int j = 0; j < 8; j++)
#pragma unroll
            for (int q = 0; q < 4; q++) acc[i][j][q] = 0.f;

    auto stage_load = [&](int it, int s) {
        uint32_t st = sbase + (uint32_t)s * STG;
        int kb = it * GBK;
#pragma unroll
        for (int u = 0; u < 4; u++) {
            int idx = tid + u * 256;
            int r = idx >> 3, c = idx & 7;
            uint32_t so = ((uint32_t)r << 7) | ((uint32_t)((c ^ (r & 7))) << 4);
            cp16(st + so, Ah + (size_t)(mrow + r) * HD1 + kb + c * 8);
            cp16(st + 16384u + so, Bh + (size_t)(ncol + r) * HD1 + kb + c * 8);
        }
        asm volatile("cp.async.commit_group;");
    };

    auto compute = [&](int s) {
        uint32_t sA = sbase + (uint32_t)s * STG;
        uint32_t sB = sA + 16384u;
#pragma unroll
        for (int ks = 0; ks < 4; ks++) {
            uint32_t a[2][4];
#pragma unroll
            for (int mr = 0; mr < 2; mr++) {
                int row = wm + mr * 16 + (lane & 15);
                int ch = ks * 2 + (lane >> 4);
                ldsm4(a[mr], sA + ((uint32_t)row << 7) + ((uint32_t)((ch ^ (row & 7))) << 4));
            }
            uint32_t b[4][4];
#pragma unroll
            for (int nb = 0; nb < 4; nb++) {
                int n = wn + nb * 16 + (lane & 7) + ((lane >> 4) << 3);
                int ch = ks * 2 + ((lane >> 3) & 1);
                ldsm4(b[nb], sB + ((uint32_t)n << 7) + ((uint32_t)((ch ^ (n & 7))) << 4));
            }
#pragma unroll
            for (int mr = 0; mr < 2; mr++)
#pragma unroll
                for (int nb = 0; nb < 4; nb++)
#pragma unroll
                    for (int hf = 0; hf < 2; hf++)
                        mma16816(acc[mr][nb * 2 + hf], a[mr], &b[nb][hf * 2]);
        }
    };

    stage_load(0, 0);
    stage_load(1, 1);
    for (int it = 0; it < KCH; it++) {
        if (it + 2 < KCH) {
            stage_load(it + 2, (it + 2) % NSTAGE);
            asm volatile("cp.async.wait_group 2;" ::: "memory");
        } else if (it + 1 < KCH) {
            asm volatile("cp.async.wait_group 1;" ::: "memory");
        } else {
            asm volatile("cp.async.wait_group 0;" ::: "memory");
        }
        __syncthreads();
        compute(it % NSTAGE);
        __syncthreads();
    }

    // ---- store C (fp16) ----
#pragma unroll
    for (int mr = 0; mr < 2; mr++)
#pragma unroll
        for (int n8 = 0; n8 < 8; n8++) {
            int row = mrow + wm + mr * 16 + (lane >> 2);
            int col = ncol + wn + n8 * 8 + (lane & 3) * 2;
            float* d = acc[mr][n8];
            if (row < M)
                *(__half2*)(C + (size_t)row * HD1 + col) = __floats2half2_rn(d[0], d[1]);
            if (row + 8 < M)
                *(__half2*)(C + (size_t)(row + 8) * HD1 + col) = __floats2half2_rn(d[2], d[3]);
        }

    // ---- fused attention-score partials: el[n,h] += h.al, er[n,h] += h.ar ----
    {
        int h = ncol >> 8;                       // head index (ncol / 256)
        int cb = (ncol & 255) + wn + (lane & 3) * 2;   // within-head col of d[0]
        float2 alv[8], arv[8];
        bool wanter = (mrow < NDST0);
#pragma unroll
        for (int n8 = 0; n8 < 8; n8++) {
            int cc = h * ND1 + cb + n8 * 8;
            alv[n8] = make_float2(__ldg(al1 + cc), __ldg(al1 + cc + 1));
            if (wanter) arv[n8] = make_float2(__ldg(ar1 + cc), __ldg(ar1 + cc + 1));
        }
        float pe[4] = {0.f, 0.f, 0.f, 0.f};
        float pr[4] = {0.f, 0.f, 0.f, 0.f};
#pragma unroll
        for (int mr = 0; mr < 2; mr++)
#pragma unroll
            for (int n8 = 0; n8 < 8; n8++) {
                float* d = acc[mr][n8];
                pe[mr * 2 + 0] += d[0] * alv[n8].x + d[1] * alv[n8].y;
                pe[mr * 2 + 1] += d[2] * alv[n8].x + d[3] * alv[n8].y;
                if (wanter) {
                    pr[mr * 2 + 0] += d[0] * arv[n8].x + d[1] * arv[n8].y;
                    pr[mr * 2 + 1] += d[2] * arv[n8].x + d[3] * arv[n8].y;
                }
            }
#pragma unroll
        for (int q = 0; q < 4; q++) {
            pe[q] += __shfl_xor_sync(0xffffffffu, pe[q], 1);
            pe[q] += __shfl_xor_sync(0xffffffffu, pe[q], 2);
            pr[q] += __shfl_xor_sync(0xffffffffu, pr[q], 1);
            pr[q] += __shfl_xor_sync(0xffffffffu, pr[q], 2);
        }
        if ((lane & 3) == 0) {
            int rbase = mrow + wm + (lane >> 2);
#pragma unroll
            for (int q = 0; q < 4; q++) {
                int r = rbase + (q & 1) * 8 + (q >> 1) * 16;
                if (r < NSRC0) atomicAdd(&el[r * NH1 + h], pe[q]);
                if (wanter && r < NDST0) atomicAdd(&er[r * NH1 + h], pr[q]);
            }
        }
    }
}

// ---------------- fp32 -> fp16 conversions (vectorized) ----------------
__global__ void convA(const float* __restrict__ f, __half* __restrict__ o)
{
    size_t i = (size_t)blockIdx.x * blockDim.x + threadIdx.x;   // float4 index
    size_t n4 = (size_t)MPAD * HD1 / 4;
    if (i >= n4) return;
    float4 v;
    if (i < (size_t)NSRC0 * HD1 / 4) v = ((const float4*)f)[i];
    else v = make_float4(0.f, 0.f, 0.f, 0.f);
    ((__half2*)o)[2 * i] = __floats2half2_rn(v.x, v.y);
    ((__half2*)o)[2 * i + 1] = __floats2half2_rn(v.z, v.w);
}
// transpose W1 [K,N] -> Bt [N,K] fp16, 32x32 smem tiles (coalesced both sides)
__global__ __launch_bounds__(256) void convB(const float* __restrict__ W, __half* __restrict__ o)
{
    __shared__ float tile[32][33];
    int kb = blockIdx.x * 32, nb = blockIdx.y * 32;
    int tx = threadIdx.x & 31, ty = threadIdx.x >> 5;   // 32 x 8
#pragma unroll
    for (int r = 0; r < 32; r += 8)
        tile[ty + r][tx] = W[(size_t)(kb + ty + r) * HD1 + nb + tx];
    __syncthreads();
#pragma unroll
    for (int r = 0; r < 32; r += 8)
        o[(size_t)(nb + ty + r) * HD1 + kb + tx] = __float2half_rn(tile[tx][ty + r]);
}

// ---------------- layer-2 SGEMM + fused scores2 ----------------
// C[M,128] = A[M,256] @ B[256,128], fp32; epilogue computes
// el2[n] = h2[n,:].al2  and  er2[n] (n < NDST1) with half-warp reduces.
__global__ __launch_bounds__(256) void gemm2(
    const float* __restrict__ A, const float* __restrict__ B,
    float* __restrict__ C, int M,
    const float* __restrict__ al2, const float* __restrict__ ar2,
    float* __restrict__ el, float* __restrict__ er)
{
    const int BM = 128, BN = 128, BK = 8, TM = 8, TN = 8;
    const int K = ND1, N = ND2;
    __shared__ float As[BK][BM];
    __shared__ float Bs[BK][BN];

    int tid = threadIdx.x;
    int tx = tid & 15, ty = tid >> 4;
    int rowBase = blockIdx.y * BM;
    int aRow = tid >> 1, aCol = (tid & 1) * 4;
    int bRow = tid >> 5, bCol = (tid & 31) * 4;

    float acc[TM][TN];
#pragma unroll
    for (int i = 0; i < TM; i++)
#pragma unroll
        for (int j = 0; j < TN; j++) acc[i][j] = 0.f;

    for (int kt = 0; kt < K; kt += BK) {
        int gr = rowBase + aRow;
        float4 av = (gr < M) ? *(const float4*)(A + (size_t)gr * K + kt + aCol)
                             : make_float4(0.f, 0.f, 0.f, 0.f);
        As[aCol + 0][aRow] = av.x; As[aCol + 1][aRow] = av.y;
        As[aCol + 2][aRow] = av.z; As[aCol + 3][aRow] = av.w;
        float4 bv = *(const float4*)(B + (size_t)(kt + bRow) * N + bCol);
        *(float4*)&Bs[bRow][bCol] = bv;
        __syncthreads();
#pragma unroll
        for (int k = 0; k < BK; k++) {
            float ar_[TM], br_[TN];
#pragma unroll
            for (int i = 0; i < TM; i++) ar_[i] = As[k][ty * TM + i];
#pragma unroll
            for (int j = 0; j < TN; j++) br_[j] = Bs[k][tx * TN + j];
#pragma unroll
            for (int i = 0; i < TM; i++)
#pragma unroll
                for (int j = 0; j < TN; j++) acc[i][j] += ar_[i] * br_[j];
        }
        __syncthreads();
    }
#pragma unroll
    for (int i = 0; i < TM; i++) {
        int gr = rowBase + ty * TM + i;
        if (gr < M) {
            float* cp = C + (size_t)gr * N + tx * TN;
#pragma unroll
            for (int j = 0; j < TN; j += 4)
                *(float4*)(cp + j) = make_float4(acc[i][j], acc[i][j + 1], acc[i][j + 2], acc[i][j + 3]);
        }
    }

    // ---- fused scores2: half-warp (16 tx lanes) covers all 128 cols of 8 rows ----
    {
        float a2[TN], r2[TN];
#pragma unroll
        for (int j = 0; j < TN; j++) {
            a2[j] = __ldg(al2 + tx * TN + j);
            r2[j] = __ldg(ar2 + tx * TN + j);
        }
        float pl[TM], pr_[TM];
#pragma unroll
        for (int i = 0; i < TM; i++) {
            float sl = 0.f, sr = 0.f;
#pragma unroll
            for (int j = 0; j < TN; j++) { sl += acc[i][j] * a2[j]; sr += acc[i][j] * r2[j]; }
            pl[i] = sl; pr_[i] = sr;
        }
#pragma unroll
        for (int o = 1; o < 16; o <<= 1)
#pragma unroll
            for (int i = 0; i < TM; i++) {
                pl[i] += __shfl_xor_sync(0xffffffffu, pl[i], o);
                pr_[i] += __shfl_xor_sync(0xffffffffu, pr_[i], o);
            }
        if (tx == 0) {
#pragma unroll
            for (int i = 0; i < TM; i++) {
                int gr = rowBase + ty * TM + i;
                if (gr < M) el[gr] = pl[i];
                if (gr < NDST1) er[gr] = pr_[i];
            }
        }
    }
}

// ---------------- CSR build (both layers merged) ----------------
__global__ void count_edges2(const int* __restrict__ dst0, int ne0, int* __restrict__ cnt0,
                             const int* __restrict__ dst1, int ne1, int* __restrict__ cnt1) {
    int e = blockIdx.x * blockDim.x + threadIdx.x;
    if (e < ne0) atomicAdd(&cnt0[dst0[e]], 1);
    if (e < ne1) atomicAdd(&cnt1[dst1[e]], 1);
}
// grid=2: block 0 scans layer-1 counts, block 1 scans layer-2 counts
__global__ __launch_bounds__(1024) void scan_excl2(
    const int* __restrict__ cntA, int* __restrict__ offA, int nA,
    const int* __restrict__ cntB, int* __restrict__ offB, int nB)
{
    const int* cnt = (blockIdx.x == 0) ? cntA : cntB;
    int* off = (blockIdx.x == 0) ? offA : offB;
    int n = (blockIdx.x == 0) ? nA : nB;
    __shared__ int s[1024];
    __shared__ int stot;
    int t = threadIdx.x;
    int chunk = (n + 1023) >> 10;
    int b = t * chunk;
    int e = b + chunk; if (e > n) e = n;
    int loc = 0;
    for (int i = b; i < e; i++) loc += cnt[i];
    s[t] = loc;
    __syncthreads();
    if (t == 0) {
        int run = 0;
        for (int i = 0; i < 1024; i++) { int x = s[i]; s[i] = run; run += x; }
        stot = run;
    }
    __syncthreads();
    int run = s[t];
    for (int i = b; i < e; i++) { off[i] = run; run += cnt[i]; }
    if (t == 0) off[n] = stot;
}
__global__ void scatter_edges2(
    const int* __restrict__ src0, const int* __restrict__ dst0, int ne0,
    const int* __restrict__ off0, int* __restrict__ cur0, int* __restrict__ esrc0,
    const int* __restrict__ src1, const int* __restrict__ dst1, int ne1,
    const int* __restrict__ off1, int* __restrict__ cur1, int* __restrict__ esrc1) {
    int e = blockIdx.x * blockDim.x + threadIdx.x;
    if (e < ne0) {
        int d = dst0[e];
        esrc0[off0[d] + atomicAdd(&cur0[d], 1)] = src0[e];
    }
    if (e < ne1) {
        int d = dst1[e];
        esrc1[off1[d] + atomicAdd(&cur1[d], 1)] = src1[e];
    }
}

// ---------------- layer-1 aggregate (shift-free softmax, fp16 gather) ----------------
__global__ __launch_bounds__(256) void aggregate1(
    const __half* __restrict__ h1, const float* __restrict__ el,
    const float* __restrict__ er, const float* __restrict__ b1,
    const int* __restrict__ off, const int* __restrict__ esrc,
    float* __restrict__ hm)
{
    int d = blockIdx.x, t = threadIdx.x;
    __shared__ float s_e[256][NH1];
    __shared__ int   s_src[256];

    int s0 = off[d], s1 = off[d + 1];
    float ssum[NH1], acc[NH1], erh[NH1];
#pragma unroll
    for (int h = 0; h < NH1; h++) {
        ssum[h] = 0.f; acc[h] = 0.f;
        erh[h] = er[d * NH1 + h];
    }

    for (int base = s0; base < s1; base += 256) {
        int cn = s1 - base; if (cn > 256) cn = 256;
        if (t < cn) {
            int s = esrc[base + t];
            s_src[t] = s;
#pragma unroll
            for (int h = 0; h < NH1; h++) {
                float x = el[s * NH1 + h] + erh[h];
                x = (x > 0.f) ? x : 0.2f * x;   // leaky_relu(0.2)
                s_e[t][h] = __expf(x);          // shift-free: |x| small, no overflow
            }
        }
        __syncthreads();

        for (int j = 0; j < cn; j++) {
            const __half* hrow = h1 + (size_t)s_src[j] * HD1 + t;
#pragma unroll
            for (int h = 0; h < NH1; h++) {
                float w = s_e[j][h];
                ssum[h] += w;
                acc[h] += w * __half2float(hrow[h * ND1]);
            }
        }
        __syncthreads();
    }

    float outv = 0.f;
#pragma unroll
    for (int h = 0; h < NH1; h++) {
        float o = (ssum[h] > 0.f) ? acc[h] / ssum[h] : 0.f;
        o += b1[h * ND1 + t];
        o = fmaxf(o, 0.f);       // relu (act=True)
        outv += o;
    }
    hm[(size_t)d * ND1 + t] = outv * 0.125f;   // head mean
}

// ---------------- layer-2 aggregate (shift-free softmax) ----------------
__global__ __launch_bounds__(128) void aggregate2(
    const float* __restrict__ h2, const float* __restrict__ el,
    const float* __restrict__ er, const float* __restrict__ b2,
    const int* __restrict__ off, const int* __restrict__ esrc,
    float* __restrict__ out)
{
    int d = blockIdx.x, t = threadIdx.x;
    __shared__ float s_e[128];
    __shared__ int   s_src[128];

    int s0 = off[d], s1 = off[d + 1];
    float ssum = 0.f, acc = 0.f;
    float erh = er[d];

    for (int base = s0; base < s1; base += 128) {
        int cn = s1 - base; if (cn > 128) cn = 128;
        if (t < cn) {
            int s = esrc[base + t];
            s_src[t] = s;
            float x = el[s] + erh;
            x = (x > 0.f) ? x : 0.2f * x;
            s_e[t] = __expf(x);
        }
        __syncthreads();

        for (int j = 0; j < cn; j++) {
            float w = s_e[j];
            ssum += w;
            acc += w * h2[(size_t)s_src[j] * ND2 + t];
        }
        __syncthreads();
    }

    float o = (ssum > 0.f) ? acc / ssum : 0.f;
    out[(size_t)d * ND2 + t] = o + b2[t];
}

// ---------------- launch ----------------
extern "C" void kernel_launch(void* const* d_in, const int* in_sizes, int n_in,
                              void* d_out, int out_size)
{
    const float* feat = (const float*)d_in[0];
    const float* W1   = (const float*)d_in[1];
    const float* al1  = (const float*)d_in[2];
    const float* ar1  = (const float*)d_in[3];
    const float* b1   = (const float*)d_in[4];
    const float* W2   = (const float*)d_in[5];
    const float* al2  = (const float*)d_in[6];
    const float* ar2  = (const float*)d_in[7];
    const float* b2   = (const float*)d_in[8];
    const int* src0 = (const int*)d_in[9];
    const int* dst0 = (const int*)d_in[10];
    const int* src1 = (const int*)d_in[11];
    const int* dst1 = (const int*)d_in[12];
    float* out = (float*)d_out;

    int e0 = in_sizes[9];
    int e1 = in_sizes[11];
    int emax = (e0 > e1) ? e0 : e1;

    __half *Ahp, *Bhp, *h1p;
    float *hmp, *h2p, *el1p, *er1p, *el2p, *er2p;
    int *off1p, *cnt1p, *esrc1p, *off2p, *cnt2p, *esrc2p;
    cudaGetSymbolAddress((void**)&Ahp, g_Ah);
    cudaGetSymbolAddress((void**)&Bhp, g_Bh);
    cudaGetSymbolAddress((void**)&h1p, g_h1);
    cudaGetSymbolAddress((void**)&hmp, g_hm);
    cudaGetSymbolAddress((void**)&h2p, g_h2);
    cudaGetSymbolAddress((void**)&el1p, g_el1);
    cudaGetSymbolAddress((void**)&er1p, g_er1);
    cudaGetSymbolAddress((void**)&el2p, g_el2);
    cudaGetSymbolAddress((void**)&er2p, g_er2);
    cudaGetSymbolAddress((void**)&off1p, g_off1);
    cudaGetSymbolAddress((void**)&cnt1p, g_cnt1);
    cudaGetSymbolAddress((void**)&esrc1p, g_esrc1);
    cudaGetSymbolAddress((void**)&off2p, g_off2);
    cudaGetSymbolAddress((void**)&cnt2p, g_cnt2);
    cudaGetSymbolAddress((void**)&esrc2p, g_esrc2);

    // ---- layer 1: fp16 mma.sync GEMM + fused scores ----
    {
        size_t n4 = (size_t)MPAD * HD1 / 4;
        convA<<<(unsigned)((n4 + 255) / 256), 256>>>(feat, Ahp);
        convB<<<dim3(HD1 / 32, HD1 / 32), 256>>>(W1, Bhp);
        cudaMemsetAsync(el1p, 0, (size_t)NSRC0 * NH1 * sizeof(float));
        cudaMemsetAsync(er1p, 0, (size_t)NDST0 * NH1 * sizeof(float));

        const int SMEM_GEMM = NSTAGE * STG;  // 96 KB
        cudaFuncSetAttribute(gemm_mma, cudaFuncAttributeMaxDynamicSharedMemorySize, SMEM_GEMM);
        dim3 grid(HD1 / GBN, MPAD / GBM);   // (16, 469)
        gemm_mma<<<grid, 256, SMEM_GEMM>>>(Ahp, Bhp, h1p, NSRC0,
                                           al1, ar1, el1p, er1p);
    }

    // ---- merged CSR build for both layers ----
    cudaMemsetAsync(cnt1p, 0, NDST0 * sizeof(int));
    cudaMemsetAsync(cnt2p, 0, NDST1 * sizeof(int));
    count_edges2<<<(emax + 255) / 256, 256>>>(dst0, e0, cnt1p, dst1, e1, cnt2p);
    scan_excl2<<<2, 1024>>>(cnt1p, off1p, NDST0, cnt2p, off2p, NDST1);
    cudaMemsetAsync(cnt1p, 0, NDST0 * sizeof(int));
    cudaMemsetAsync(cnt2p, 0, NDST1 * sizeof(int));
    scatter_edges2<<<(emax + 255) / 256, 256>>>(src0, dst0, e0, off1p, cnt1p, esrc1p,
                                                src1, dst1, e1, off2p, cnt2p, esrc2p);

    aggregate1<<<NDST0, 256>>>(h1p, el1p, er1p, b1, off1p, esrc1p, hmp);

    // ---- layer 2: SGEMM + fused scores2 ----
    {
        dim3 grid(1, (NDST0 + 127) / 128);
        gemm2<<<grid, 256>>>(hmp, W2, h2p, NDST0, al2, ar2, el2p, er2p);
    }

    aggregate2<<<NDST1, 128>>>(h2p, el2p, er2p, b2, off2p, esrc2p, out);
}

// round 13
// speedup vs baseline: 1.1793x; 1.0650x over previous
#include <cuda_runtime.h>
#include <cuda_fp16.h>
#include <cstdint>

// ---------------- problem constants ----------------
#define NSRC0 60000
#define MPAD  60032    // 469 * 128
#define NDST0 15000
#define NDST1 4000
#define NH1   8
#define ND1   256
#define ND2   128
#define HD1   2048   // NH1*ND1 (also IN_DIM)
#define E0MAX 240000
#define E1MAX 64000

// ---------------- device scratch (static, allowed) ----------------
__device__ __half g_Ah[(size_t)MPAD * HD1];          // 246 MB (fp16 feat)
__device__ __half g_Bh[(size_t)HD1 * HD1];           // 8.4 MB (transposed W1: [N,K], fp16)
__device__ __half g_h1[(size_t)NSRC0 * HD1];         // 246 MB (fp16 h1)
__device__ float g_el1[NSRC0 * NH1];
__device__ float g_er1[NDST0 * NH1];
__device__ int   g_off1[NDST0 + 1];
__device__ int   g_cnt1[NDST0];
__device__ int   g_esrc1[E0MAX];
__device__ float g_hm[(size_t)NDST0 * ND1];
__device__ float g_h2[(size_t)NDST0 * ND2];
__device__ float g_el2[NDST0];
__device__ float g_er2[NDST1];
__device__ int   g_off2[NDST1 + 1];
__device__ int   g_cnt2[NDST1];
__device__ int   g_esrc2[E1MAX];

// =====================================================================
// mma.sync fp16 GEMM (R9 config — best measured: 1117us, tensor=74%)
// C[M,2048] = A @ B^T (fp16 out).  Bt is [N,K].
// CTA 128x128, BK=64, 3-stage cp.async, 256 threads, warp tile 32x64,
// __launch_bounds__(256,2) -> 128 regs, 2 CTAs/SM (2x96KB smem).
// Fused epilogue: el/er attention-score partials via atomicAdd.
// =====================================================================
static __device__ __forceinline__ void cp16(uint32_t s, const void* g) {
    asm volatile("cp.async.cg.shared.global [%0], [%1], 16;" :: "r"(s), "l"(g));
}
static __device__ __forceinline__ void ldsm4(uint32_t* r, uint32_t addr) {
    asm volatile("ldmatrix.sync.aligned.m8n8.x4.shared.b16 {%0,%1,%2,%3}, [%4];"
                 : "=r"(r[0]), "=r"(r[1]), "=r"(r[2]), "=r"(r[3]) : "r"(addr));
}
static __device__ __forceinline__ void mma16816(float* d, const uint32_t* a, const uint32_t* b) {
    asm volatile(
        "mma.sync.aligned.m16n8k16.row.col.f32.f16.f16.f32 "
        "{%0,%1,%2,%3}, {%4,%5,%6,%7}, {%8,%9}, {%0,%1,%2,%3};"
        : "+f"(d[0]), "+f"(d[1]), "+f"(d[2]), "+f"(d[3])
        : "r"(a[0]), "r"(a[1]), "r"(a[2]), "r"(a[3]), "r"(b[0]), "r"(b[1]));
}

#define GBM 128
#define GBN 128
#define GBK 64
#define KCH (HD1 / GBK)        // 32
#define STG 32768              // A 16KB + B 16KB per stage (128 rows x 128B)
#define NSTAGE 3

__global__ __launch_bounds__(256, 2) void gemm_mma(
    const __half* __restrict__ Ah, const __half* __restrict__ Bh,
    __half* __restrict__ C, int M,
    const float* __restrict__ al1, const float* __restrict__ ar1,
    float* __restrict__ el, float* __restrict__ er)
{
    extern __shared__ __align__(128) char smem[];
    uint32_t sbase = (uint32_t)__cvta_generic_to_shared(smem);

    int tid = threadIdx.x, wid = tid >> 5, lane = tid & 31;
    int mrow = blockIdx.y * GBM;
    int ncol = blockIdx.x * GBN;
    int wm = (wid & 3) * 32;       // warp row base in tile
    int wn = (wid >> 2) * 64;      // warp col base in tile

    float acc[2][8][4];
#pragma unroll
    for (int i = 0; i < 2; i++)
#pragma unroll
        for (int j = 0; j < 8; j++)
#pragma unroll
            for (int q = 0; q < 4; q++) acc[i][j][q] = 0.f;

    auto stage_load = [&](int it, int s) {
        uint32_t st = sbase + (uint32_t)s * STG;
        int kb = it * GBK;
#pragma unroll
        for (int u = 0; u < 4; u++) {
            int idx = tid + u * 256;
            int r = idx >> 3, c = idx & 7;
            uint32_t so = ((uint32_t)r << 7) | ((uint32_t)((c ^ (r & 7))) << 4);
            cp16(st + so, Ah + (size_t)(mrow + r) * HD1 + kb + c * 8);
            cp16(st + 16384u + so, Bh + (size_t)(ncol + r) * HD1 + kb + c * 8);
        }
        asm volatile("cp.async.commit_group;");
    };

    auto compute = [&](int s) {
        uint32_t sA = sbase + (uint32_t)s * STG;
        uint32_t sB = sA + 16384u;
#pragma unroll
        for (int ks = 0; ks < 4; ks++) {
            uint32_t a[2][4];
#pragma unroll
            for (int mr = 0; mr < 2; mr++) {
                int row = wm + mr * 16 + (lane & 15);
                int ch = ks * 2 + (lane >> 4);
                ldsm4(a[mr], sA + ((uint32_t)row << 7) + ((uint32_t)((ch ^ (row & 7))) << 4));
            }
            uint32_t b[4][4];
#pragma unroll
            for (int nb = 0; nb < 4; nb++) {
                int n = wn + nb * 16 + (lane & 7) + ((lane >> 4) << 3);
                int ch = ks * 2 + ((lane >> 3) & 1);
                ldsm4(b[nb], sB + ((uint32_t)n << 7) + ((uint32_t)((ch ^ (n & 7))) << 4));
            }
#pragma unroll
            for (int mr = 0; mr < 2; mr++)
#pragma unroll
                for (int nb = 0; nb < 4; nb++)
#pragma unroll
                    for (int hf = 0; hf < 2; hf++)
                        mma16816(acc[mr][nb * 2 + hf], a[mr], &b[nb][hf * 2]);
        }
    };

    stage_load(0, 0);
    stage_load(1, 1);
    for (int it = 0; it < KCH; it++) {
        if (it + 2 < KCH) {
            stage_load(it + 2, (it + 2) % NSTAGE);
            asm volatile("cp.async.wait_group 2;" ::: "memory");
        } else if (it + 1 < KCH) {
            asm volatile("cp.async.wait_group 1;" ::: "memory");
        } else {
            asm volatile("cp.async.wait_group 0;" ::: "memory");
        }
        __syncthreads();
        compute(it % NSTAGE);
        __syncthreads();
    }

    // ---- store C (fp16) ----
#pragma unroll
    for (int mr = 0; mr < 2; mr++)
#pragma unroll
        for (int n8 = 0; n8 < 8; n8++) {
            int row = mrow + wm + mr * 16 + (lane >> 2);
            int col = ncol + wn + n8 * 8 + (lane & 3) * 2;
            float* d = acc[mr][n8];
            if (row < M)
                *(__half2*)(C + (size_t)row * HD1 + col) = __floats2half2_rn(d[0], d[1]);
            if (row + 8 < M)
                *(__half2*)(C + (size_t)(row + 8) * HD1 + col) = __floats2half2_rn(d[2], d[3]);
        }

    // ---- fused attention-score partials: el[n,h] += h.al, er[n,h] += h.ar ----
    {
        int h = ncol >> 8;                       // head index (ncol / 256)
        int cb = (ncol & 255) + wn + (lane & 3) * 2;   // within-head col of d[0]
        float2 alv[8], arv[8];
        bool wanter = (mrow < NDST0);
#pragma unroll
        for (int n8 = 0; n8 < 8; n8++) {
            int cc = h * ND1 + cb + n8 * 8;
            alv[n8] = make_float2(__ldg(al1 + cc), __ldg(al1 + cc + 1));
            if (wanter) arv[n8] = make_float2(__ldg(ar1 + cc), __ldg(ar1 + cc + 1));
        }
        float pe[4] = {0.f, 0.f, 0.f, 0.f};
        float pr[4] = {0.f, 0.f, 0.f, 0.f};
#pragma unroll
        for (int mr = 0; mr < 2; mr++)
#pragma unroll
            for (int n8 = 0; n8 < 8; n8++) {
                float* d = acc[mr][n8];
                pe[mr * 2 + 0] += d[0] * alv[n8].x + d[1] * alv[n8].y;
                pe[mr * 2 + 1] += d[2] * alv[n8].x + d[3] * alv[n8].y;
                if (wanter) {
                    pr[mr * 2 + 0] += d[0] * arv[n8].x + d[1] * arv[n8].y;
                    pr[mr * 2 + 1] += d[2] * arv[n8].x + d[3] * arv[n8].y;
                }
            }
#pragma unroll
        for (int q = 0; q < 4; q++) {
            pe[q] += __shfl_xor_sync(0xffffffffu, pe[q], 1);
            pe[q] += __shfl_xor_sync(0xffffffffu, pe[q], 2);
            pr[q] += __shfl_xor_sync(0xffffffffu, pr[q], 1);
            pr[q] += __shfl_xor_sync(0xffffffffu, pr[q], 2);
        }
        if ((lane & 3) == 0) {
            int rbase = mrow + wm + (lane >> 2);
#pragma unroll
            for (int q = 0; q < 4; q++) {
                int r = rbase + (q & 1) * 8 + (q >> 1) * 16;
                if (r < NSRC0) atomicAdd(&el[r * NH1 + h], pe[q]);
                if (wanter && r < NDST0) atomicAdd(&er[r * NH1 + h], pr[q]);
            }
        }
    }
}

// ---------------- fp32 -> fp16 conversions (vectorized) ----------------
__global__ void convA(const float* __restrict__ f, __half* __restrict__ o)
{
    size_t i = (size_t)blockIdx.x * blockDim.x + threadIdx.x;   // float4 index
    size_t n4 = (size_t)MPAD * HD1 / 4;
    if (i >= n4) return;
    float4 v;
    if (i < (size_t)NSRC0 * HD1 / 4) v = ((const float4*)f)[i];
    else v = make_float4(0.f, 0.f, 0.f, 0.f);
    ((__half2*)o)[2 * i] = __floats2half2_rn(v.x, v.y);
    ((__half2*)o)[2 * i + 1] = __floats2half2_rn(v.z, v.w);
}
// transpose W1 [K,N] -> Bt [N,K] fp16, 32x32 smem tiles (coalesced both sides)
__global__ __launch_bounds__(256) void convB(const float* __restrict__ W, __half* __restrict__ o)
{
    __shared__ float tile[32][33];
    int kb = blockIdx.x * 32, nb = blockIdx.y * 32;
    int tx = threadIdx.x & 31, ty = threadIdx.x >> 5;   // 32 x 8
#pragma unroll
    for (int r = 0; r < 32; r += 8)
        tile[ty + r][tx] = W[(size_t)(kb + ty + r) * HD1 + nb + tx];
    __syncthreads();
#pragma unroll
    for (int r = 0; r < 32; r += 8)
        o[(size_t)(nb + ty + r) * HD1 + kb + tx] = __float2half_rn(tile[tx][ty + r]);
}

// ---------------- layer-2 SGEMM + fused scores2 ----------------
__global__ __launch_bounds__(256) void gemm2(
    const float* __restrict__ A, const float* __restrict__ B,
    float* __restrict__ C, int M,
    const float* __restrict__ al2, const float* __restrict__ ar2,
    float* __restrict__ el, float* __restrict__ er)
{
    const int BM = 128, BN = 128, BK = 8, TM = 8, TN = 8;
    const int K = ND1, N = ND2;
    __shared__ float As[BK][BM];
    __shared__ float Bs[BK][BN];

    int tid = threadIdx.x;
    int tx = tid & 15, ty = tid >> 4;
    int rowBase = blockIdx.y * BM;
    int aRow = tid >> 1, aCol = (tid & 1) * 4;
    int bRow = tid >> 5, bCol = (tid & 31) * 4;

    float acc[TM][TN];
#pragma unroll
    for (int i = 0; i < TM; i++)
#pragma unroll
        for (int j = 0; j < TN; j++) acc[i][j] = 0.f;

    for (int kt = 0; kt < K; kt += BK) {
        int gr = rowBase + aRow;
        float4 av = (gr < M) ? *(const float4*)(A + (size_t)gr * K + kt + aCol)
                             : make_float4(0.f, 0.f, 0.f, 0.f);
        As[aCol + 0][aRow] = av.x; As[aCol + 1][aRow] = av.y;
        As[aCol + 2][aRow] = av.z; As[aCol + 3][aRow] = av.w;
        float4 bv = *(const float4*)(B + (size_t)(kt + bRow) * N + bCol);
        *(float4*)&Bs[bRow][bCol] = bv;
        __syncthreads();
#pragma unroll
        for (int k = 0; k < BK; k++) {
            float ar_[TM], br_[TN];
#pragma unroll
            for (int i = 0; i < TM; i++) ar_[i] = As[k][ty * TM + i];
#pragma unroll
            for (int j = 0; j < TN; j++) br_[j] = Bs[k][tx * TN + j];
#pragma unroll
            for (int i = 0; i < TM; i++)
#pragma unroll
                for (int j = 0; j < TN; j++) acc[i][j] += ar_[i] * br_[j];
        }
        __syncthreads();
    }
#pragma unroll
    for (int i = 0; i < TM; i++) {
        int gr = rowBase + ty * TM + i;
        if (gr < M) {
            float* cp = C + (size_t)gr * N + tx * TN;
#pragma unroll
            for (int j = 0; j < TN; j += 4)
                *(float4*)(cp + j) = make_float4(acc[i][j], acc[i][j + 1], acc[i][j + 2], acc[i][j + 3]);
        }
    }

    // ---- fused scores2: half-warp (16 tx lanes) covers all 128 cols of 8 rows ----
    {
        float a2[TN], r2[TN];
#pragma unroll
        for (int j = 0; j < TN; j++) {
            a2[j] = __ldg(al2 + tx * TN + j);
            r2[j] = __ldg(ar2 + tx * TN + j);
        }
        float pl[TM], pr_[TM];
#pragma unroll
        for (int i = 0; i < TM; i++) {
            float sl = 0.f, sr = 0.f;
#pragma unroll
            for (int j = 0; j < TN; j++) { sl += acc[i][j] * a2[j]; sr += acc[i][j] * r2[j]; }
            pl[i] = sl; pr_[i] = sr;
        }
#pragma unroll
        for (int o = 1; o < 16; o <<= 1)
#pragma unroll
            for (int i = 0; i < TM; i++) {
                pl[i] += __shfl_xor_sync(0xffffffffu, pl[i], o);
                pr_[i] += __shfl_xor_sync(0xffffffffu, pr_[i], o);
            }
        if (tx == 0) {
#pragma unroll
            for (int i = 0; i < TM; i++) {
                int gr = rowBase + ty * TM + i;
                if (gr < M) el[gr] = pl[i];
                if (gr < NDST1) er[gr] = pr_[i];
            }
        }
    }
}

// ---------------- CSR build (both layers merged) ----------------
__global__ void count_edges2(const int* __restrict__ dst0, int ne0, int* __restrict__ cnt0,
                             const int* __restrict__ dst1, int ne1, int* __restrict__ cnt1) {
    int e = blockIdx.x * blockDim.x + threadIdx.x;
    if (e < ne0) atomicAdd(&cnt0[dst0[e]], 1);
    if (e < ne1) atomicAdd(&cnt1[dst1[e]], 1);
}
__global__ __launch_bounds__(1024) void scan_excl2(
    const int* __restrict__ cntA, int* __restrict__ offA, int nA,
    const int* __restrict__ cntB, int* __restrict__ offB, int nB)
{
    const int* cnt = (blockIdx.x == 0) ? cntA : cntB;
    int* off = (blockIdx.x == 0) ? offA : offB;
    int n = (blockIdx.x == 0) ? nA : nB;
    __shared__ int s[1024];
    __shared__ int stot;
    int t = threadIdx.x;
    int chunk = (n + 1023) >> 10;
    int b = t * chunk;
    int e = b + chunk; if (e > n) e = n;
    int loc = 0;
    for (int i = b; i < e; i++) loc += cnt[i];
    s[t] = loc;
    __syncthreads();
    if (t == 0) {
        int run = 0;
        for (int i = 0; i < 1024; i++) { int x = s[i]; s[i] = run; run += x; }
        stot = run;
    }
    __syncthreads();
    int run = s[t];
    for (int i = b; i < e; i++) { off[i] = run; run += cnt[i]; }
    if (t == 0) off[n] = stot;
}
__global__ void scatter_edges2(
    const int* __restrict__ src0, const int* __restrict__ dst0, int ne0,
    const int* __restrict__ off0, int* __restrict__ cur0, int* __restrict__ esrc0,
    const int* __restrict__ src1, const int* __restrict__ dst1, int ne1,
    const int* __restrict__ off1, int* __restrict__ cur1, int* __restrict__ esrc1) {
    int e = blockIdx.x * blockDim.x + threadIdx.x;
    if (e < ne0) {
        int d = dst0[e];
        esrc0[off0[d] + atomicAdd(&cur0[d], 1)] = src0[e];
    }
    if (e < ne1) {
        int d = dst1[e];
        esrc1[off1[d] + atomicAdd(&cur1[d], 1)] = src1[e];
    }
}

// ---------------- layer-1 aggregate: head-per-warp vectorized gather ----------------
// warp w owns head w; lane l owns dims [l*8, l*8+8) of that head.
// Per edge each warp issues ONE LDG.128 (vs 8 scattered LDG.32 before).
__global__ __launch_bounds__(256) void aggregate1(
    const __half* __restrict__ h1, const float* __restrict__ el,
    const float* __restrict__ er, const float* __restrict__ b1,
    const int* __restrict__ off, const int* __restrict__ esrc,
    float* __restrict__ hm)
{
    int d = blockIdx.x, t = threadIdx.x;
    int wid = t >> 5, lane = t & 31;
    __shared__ float s_e[256][NH1];        // 8 KB  (edge weights, all heads)
    __shared__ int   s_src[256];
    __shared__ float s_out[NH1][ND1];      // 8 KB  (per-head relu'd outputs)

    int s0 = off[d], s1 = off[d + 1];
    float ssum = 0.f;
    float acc[8];
#pragma unroll
    for (int k = 0; k < 8; k++) acc[k] = 0.f;
    float erh[NH1];
#pragma unroll
    for (int h = 0; h < NH1; h++) erh[h] = er[d * NH1 + h];

    for (int base = s0; base < s1; base += 256) {
        int cn = s1 - base; if (cn > 256) cn = 256;
        if (t < cn) {
            int s = esrc[base + t];
            s_src[t] = s;
#pragma unroll
            for (int h = 0; h < NH1; h++) {
                float x = el[s * NH1 + h] + erh[h];
                x = (x > 0.f) ? x : 0.2f * x;   // leaky_relu(0.2)
                s_e[t][h] = __expf(x);          // shift-free: |x| small, no overflow
            }
        }
        __syncthreads();

#pragma unroll 2
        for (int j = 0; j < cn; j++) {
            float w = s_e[j][wid];              // smem broadcast
            ssum += w;
            const uint4 v = *(const uint4*)(h1 + (size_t)s_src[j] * HD1 + wid * ND1 + lane * 8);
            float2 f0 = __half22float2(*(const __half2*)&v.x);
            float2 f1 = __half22float2(*(((const __half2*)&v.x) + 1));
            float2 f2 = __half22float2(*(const __half2*)&v.z);
            float2 f3 = __half22float2(*(((const __half2*)&v.z) + 1));
            acc[0] += w * f0.x; acc[1] += w * f0.y;
            acc[2] += w * f1.x; acc[3] += w * f1.y;
            acc[4] += w * f2.x; acc[5] += w * f2.y;
            acc[6] += w * f3.x; acc[7] += w * f3.y;
        }
        __syncthreads();
    }

    // finalize this head's 8 dims: /ssum + bias, relu -> smem
    float inv = (ssum > 0.f) ? 1.f / ssum : 0.f;
#pragma unroll
    for (int k = 0; k < 8; k++) {
        float o = acc[k] * inv + b1[wid * ND1 + lane * 8 + k];
        s_out[wid][lane * 8 + k] = fmaxf(o, 0.f);
    }
    __syncthreads();

    // head mean: thread t handles dim t across all 8 heads
    float sum = 0.f;
#pragma unroll
    for (int h = 0; h < NH1; h++) sum += s_out[h][t];
    hm[(size_t)d * ND1 + t] = sum * 0.125f;
}

// ---------------- layer-2 aggregate (shift-free softmax) ----------------
__global__ __launch_bounds__(128) void aggregate2(
    const float* __restrict__ h2, const float* __restrict__ el,
    const float* __restrict__ er, const float* __restrict__ b2,
    const int* __restrict__ off, const int* __restrict__ esrc,
    float* __restrict__ out)
{
    int d = blockIdx.x, t = threadIdx.x;
    __shared__ float s_e[128];
    __shared__ int   s_src[128];

    int s0 = off[d], s1 = off[d + 1];
    float ssum = 0.f, acc = 0.f;
    float erh = er[d];

    for (int base = s0; base < s1; base += 128) {
        int cn = s1 - base; if (cn > 128) cn = 128;
        if (t < cn) {
            int s = esrc[base + t];
            s_src[t] = s;
            float x = el[s] + erh;
            x = (x > 0.f) ? x : 0.2f * x;
            s_e[t] = __expf(x);
        }
        __syncthreads();

#pragma unroll 2
        for (int j = 0; j < cn; j++) {
            float w = s_e[j];
            ssum += w;
            acc += w * h2[(size_t)s_src[j] * ND2 + t];
        }
        __syncthreads();
    }

    float o = (ssum > 0.f) ? acc / ssum : 0.f;
    out[(size_t)d * ND2 + t] = o + b2[t];
}

// ---------------- launch ----------------
extern "C" void kernel_launch(void* const* d_in, const int* in_sizes, int n_in,
                              void* d_out, int out_size)
{
    const float* feat = (const float*)d_in[0];
    const float* W1   = (const float*)d_in[1];
    const float* al1  = (const float*)d_in[2];
    const float* ar1  = (const float*)d_in[3];
    const float* b1   = (const float*)d_in[4];
    const float* W2   = (const float*)d_in[5];
    const float* al2  = (const float*)d_in[6];
    const float* ar2  = (const float*)d_in[7];
    const float* b2   = (const float*)d_in[8];
    const int* src0 = (const int*)d_in[9];
    const int* dst0 = (const int*)d_in[10];
    const int* src1 = (const int*)d_in[11];
    const int* dst1 = (const int*)d_in[12];
    float* out = (float*)d_out;

    int e0 = in_sizes[9];
    int e1 = in_sizes[11];
    int emax = (e0 > e1) ? e0 : e1;

    __half *Ahp, *Bhp, *h1p;
    float *hmp, *h2p, *el1p, *er1p, *el2p, *er2p;
    int *off1p, *cnt1p, *esrc1p, *off2p, *cnt2p, *esrc2p;
    cudaGetSymbolAddress((void**)&Ahp, g_Ah);
    cudaGetSymbolAddress((void**)&Bhp, g_Bh);
    cudaGetSymbolAddress((void**)&h1p, g_h1);
    cudaGetSymbolAddress((void**)&hmp, g_hm);
    cudaGetSymbolAddress((void**)&h2p, g_h2);
    cudaGetSymbolAddress((void**)&el1p, g_el1);
    cudaGetSymbolAddress((void**)&er1p, g_er1);
    cudaGetSymbolAddress((void**)&el2p, g_el2);
    cudaGetSymbolAddress((void**)&er2p, g_er2);
    cudaGetSymbolAddress((void**)&off1p, g_off1);
    cudaGetSymbolAddress((void**)&cnt1p, g_cnt1);
    cudaGetSymbolAddress((void**)&esrc1p, g_esrc1);
    cudaGetSymbolAddress((void**)&off2p, g_off2);
    cudaGetSymbolAddress((void**)&cnt2p, g_cnt2);
    cudaGetSymbolAddress((void**)&esrc2p, g_esrc2);

    // ---- layer 1: fp16 mma.sync GEMM + fused scores ----
    {
        size_t n4 = (size_t)MPAD * HD1 / 4;
        convA<<<(unsigned)((n4 + 255) / 256), 256>>>(feat, Ahp);
        convB<<<dim3(HD1 / 32, HD1 / 32), 256>>>(W1, Bhp);
        cudaMemsetAsync(el1p, 0, (size_t)NSRC0 * NH1 * sizeof(float));
        cudaMemsetAsync(er1p, 0, (size_t)NDST0 * NH1 * sizeof(float));

        const int SMEM_GEMM = NSTAGE * STG;  // 96 KB
        cudaFuncSetAttribute(gemm_mma, cudaFuncAttributeMaxDynamicSharedMemorySize, SMEM_GEMM);
        dim3 grid(HD1 / GBN, MPAD / GBM);   // (16, 469)
        gemm_mma<<<grid, 256, SMEM_GEMM>>>(Ahp, Bhp, h1p, NSRC0,
                                           al1, ar1, el1p, er1p);
    }

    // ---- merged CSR build for both layers ----
    cudaMemsetAsync(cnt1p, 0, NDST0 * sizeof(int));
    cudaMemsetAsync(cnt2p, 0, NDST1 * sizeof(int));
    count_edges2<<<(emax + 255) / 256, 256>>>(dst0, e0, cnt1p, dst1, e1, cnt2p);
    scan_excl2<<<2, 1024>>>(cnt1p, off1p, NDST0, cnt2p, off2p, NDST1);
    cudaMemsetAsync(cnt1p, 0, NDST0 * sizeof(int));
    cudaMemsetAsync(cnt2p, 0, NDST1 * sizeof(int));
    scatter_edges2<<<(emax + 255) / 256, 256>>>(src0, dst0, e0, off1p, cnt1p, esrc1p,
                                                src1, dst1, e1, off2p, cnt2p, esrc2p);

    aggregate1<<<NDST0, 256>>>(h1p, el1p, er1p, b1, off1p, esrc1p, hmp);

    // ---- layer 2: SGEMM + fused scores2 ----
    {
        dim3 grid(1, (NDST0 + 127) / 128);
        gemm2<<<grid, 256>>>(hmp, W2, h2p, NDST0, al2, ar2, el2p, er2p);
    }

    aggregate2<<<NDST1, 128>>>(h2p, el2p, er2p, b2, off2p, esrc2p, out);
}

// round 14
// speedup vs baseline: 1.1867x; 1.0063x over previous
#include <cuda_runtime.h>
#include <cuda_fp16.h>
#include <cstdint>

// ---------------- problem constants ----------------
#define NSRC0 60000
#define MPAD  60032    // 469 * 128
#define NDST0 15000
#define NDST1 4000
#define NH1   8
#define ND1   256
#define ND2   128
#define HD1   2048   // NH1*ND1 (also IN_DIM)
#define E0MAX 240000
#define E1MAX 64000

// ---------------- device scratch (static, allowed) ----------------
__device__ __half g_Ah[(size_t)MPAD * HD1];          // 246 MB (fp16 feat)
__device__ __half g_Bh[(size_t)HD1 * HD1];           // 8.4 MB (transposed W1: [N,K], fp16)
__device__ __half g_h1[(size_t)NSRC0 * HD1];         // 246 MB (fp16 h1)
__device__ float g_el1[NSRC0 * NH1];
__device__ float g_er1[NDST0 * NH1];
__device__ int   g_off1[NDST0 + 1];
__device__ int   g_cnt1[NDST0];
__device__ int   g_esrc1[E0MAX];
__device__ float g_hm[(size_t)NDST0 * ND1];
__device__ float g_h2[(size_t)NDST0 * ND2];
__device__ float g_el2[NDST0];
__device__ float g_er2[NDST1];
__device__ int   g_off2[NDST1 + 1];
__device__ int   g_cnt2[NDST1];
__device__ int   g_esrc2[E1MAX];

// =====================================================================
// mma.sync fp16 GEMM: C[M,2048] = A @ B^T (fp16 out).  Bt is [N,K].
// CTA 128x128, BK=64, 3-stage cp.async, 256 threads, warp tile 32x64,
// __launch_bounds__(256,2) -> 128 regs, 2 CTAs/SM (2x96KB smem).
// ONE __syncthreads per mainloop iter (CUTLASS multistage ordering):
//   wait_group(1); sync; load(it+2); compute(it)
// Fused epilogue: el/er attention-score partials via atomicAdd.
// =====================================================================
static __device__ __forceinline__ void cp16(uint32_t s, const void* g) {
    asm volatile("cp.async.cg.shared.global [%0], [%1], 16;" :: "r"(s), "l"(g));
}
static __device__ __forceinline__ void ldsm4(uint32_t* r, uint32_t addr) {
    asm volatile("ldmatrix.sync.aligned.m8n8.x4.shared.b16 {%0,%1,%2,%3}, [%4];"
                 : "=r"(r[0]), "=r"(r[1]), "=r"(r[2]), "=r"(r[3]) : "r"(addr));
}
static __device__ __forceinline__ void mma16816(float* d, const uint32_t* a, const uint32_t* b) {
    asm volatile(
        "mma.sync.aligned.m16n8k16.row.col.f32.f16.f16.f32 "
        "{%0,%1,%2,%3}, {%4,%5,%6,%7}, {%8,%9}, {%0,%1,%2,%3};"
        : "+f"(d[0]), "+f"(d[1]), "+f"(d[2]), "+f"(d[3])
        : "r"(a[0]), "r"(a[1]), "r"(a[2]), "r"(a[3]), "r"(b[0]), "r"(b[1]));
}

#define GBM 128
#define GBN 128
#define GBK 64
#define KCH (HD1 / GBK)        // 32
#define STG 32768              // A 16KB + B 16KB per stage (128 rows x 128B)
#define NSTAGE 3

__global__ __launch_bounds__(256, 2) void gemm_mma(
    const __half* __restrict__ Ah, const __half* __restrict__ Bh,
    __half* __restrict__ C, int M,
    const float* __restrict__ al1, const float* __restrict__ ar1,
    float* __restrict__ el, float* __restrict__ er)
{
    extern __shared__ __align__(128) char smem[];
    uint32_t sbase = (uint32_t)__cvta_generic_to_shared(smem);

    int tid = threadIdx.x, wid = tid >> 5, lane = tid & 31;
    int mrow = blockIdx.y * GBM;
    int ncol = blockIdx.x * GBN;
    int wm = (wid & 3) * 32;       // warp row base in tile
    int wn = (wid >> 2) * 64;      // warp col base in tile

    float acc[2][8][4];
#pragma unroll
    for (int i = 0; i < 2; i++)
#pragma unroll
        for (int j = 0; j < 8; j++)
#pragma unroll
            for (int q = 0; q < 4; q++) acc[i][j][q] = 0.f;

    auto stage_load = [&](int it, int s) {
        uint32_t st = sbase + (uint32_t)s * STG;
        int kb = it * GBK;
#pragma unroll
        for (int u = 0; u < 4; u++) {
            int idx = tid + u * 256;
            int r = idx >> 3, c = idx & 7;
            uint32_t so = ((uint32_t)r << 7) | ((uint32_t)((c ^ (r & 7))) << 4);
            cp16(st + so, Ah + (size_t)(mrow + r) * HD1 + kb + c * 8);
            cp16(st + 16384u + so, Bh + (size_t)(ncol + r) * HD1 + kb + c * 8);
        }
        asm volatile("cp.async.commit_group;");
    };

    auto compute = [&](int s) {
        uint32_t sA = sbase + (uint32_t)s * STG;
        uint32_t sB = sA + 16384u;
#pragma unroll
        for (int ks = 0; ks < 4; ks++) {
            uint32_t a[2][4];
#pragma unroll
            for (int mr = 0; mr < 2; mr++) {
                int row = wm + mr * 16 + (lane & 15);
                int ch = ks * 2 + (lane >> 4);
                ldsm4(a[mr], sA + ((uint32_t)row << 7) + ((uint32_t)((ch ^ (row & 7))) << 4));
            }
            uint32_t b[4][4];
#pragma unroll
            for (int nb = 0; nb < 4; nb++) {
                int n = wn + nb * 16 + (lane & 7) + ((lane >> 4) << 3);
                int ch = ks * 2 + ((lane >> 3) & 1);
                ldsm4(b[nb], sB + ((uint32_t)n << 7) + ((uint32_t)((ch ^ (n & 7))) << 4));
            }
#pragma unroll
            for (int mr = 0; mr < 2; mr++)
#pragma unroll
                for (int nb = 0; nb < 4; nb++)
#pragma unroll
                    for (int hf = 0; hf < 2; hf++)
                        mma16816(acc[mr][nb * 2 + hf], a[mr], &b[nb][hf * 2]);
        }
    };

    stage_load(0, 0);
    stage_load(1, 1);
    for (int it = 0; it < KCH; it++) {
        // ensure (own) stage-it loads done: groups pending <= 1 (stage it+1)
        if (it < KCH - 1) {
            asm volatile("cp.async.wait_group 1;" ::: "memory");
        } else {
            asm volatile("cp.async.wait_group 0;" ::: "memory");
        }
        // global visibility of stage-it data AND everyone finished compute(it-1)
        __syncthreads();
        if (it + 2 < KCH) stage_load(it + 2, (it + 2) % NSTAGE);
        compute(it % NSTAGE);
    }

    // ---- store C (fp16) ----
#pragma unroll
    for (int mr = 0; mr < 2; mr++)
#pragma unroll
        for (int n8 = 0; n8 < 8; n8++) {
            int row = mrow + wm + mr * 16 + (lane >> 2);
            int col = ncol + wn + n8 * 8 + (lane & 3) * 2;
            float* d = acc[mr][n8];
            if (row < M)
                *(__half2*)(C + (size_t)row * HD1 + col) = __floats2half2_rn(d[0], d[1]);
            if (row + 8 < M)
                *(__half2*)(C + (size_t)(row + 8) * HD1 + col) = __floats2half2_rn(d[2], d[3]);
        }

    // ---- fused attention-score partials: el[n,h] += h.al, er[n,h] += h.ar ----
    {
        int h = ncol >> 8;                       // head index (ncol / 256)
        int cb = (ncol & 255) + wn + (lane & 3) * 2;   // within-head col of d[0]
        float2 alv[8], arv[8];
        bool wanter = (mrow < NDST0);
#pragma unroll
        for (int n8 = 0; n8 < 8; n8++) {
            int cc = h * ND1 + cb + n8 * 8;
            alv[n8] = make_float2(__ldg(al1 + cc), __ldg(al1 + cc + 1));
            if (wanter) arv[n8] = make_float2(__ldg(ar1 + cc), __ldg(ar1 + cc + 1));
        }
        float pe[4] = {0.f, 0.f, 0.f, 0.f};
        float pr[4] = {0.f, 0.f, 0.f, 0.f};
#pragma unroll
        for (int mr = 0; mr < 2; mr++)
#pragma unroll
            for (int n8 = 0; n8 < 8; n8++) {
                float* d = acc[mr][n8];
                pe[mr * 2 + 0] += d[0] * alv[n8].x + d[1] * alv[n8].y;
                pe[mr * 2 + 1] += d[2] * alv[n8].x + d[3] * alv[n8].y;
                if (wanter) {
                    pr[mr * 2 + 0] += d[0] * arv[n8].x + d[1] * arv[n8].y;
                    pr[mr * 2 + 1] += d[2] * arv[n8].x + d[3] * arv[n8].y;
                }
            }
#pragma unroll
        for (int q = 0; q < 4; q++) {
            pe[q] += __shfl_xor_sync(0xffffffffu, pe[q], 1);
            pe[q] += __shfl_xor_sync(0xffffffffu, pe[q], 2);
            pr[q] += __shfl_xor_sync(0xffffffffu, pr[q], 1);
            pr[q] += __shfl_xor_sync(0xffffffffu, pr[q], 2);
        }
        if ((lane & 3) == 0) {
            int rbase = mrow + wm + (lane >> 2);
#pragma unroll
            for (int q = 0; q < 4; q++) {
                int r = rbase + (q & 1) * 8 + (q >> 1) * 16;
                if (r < NSRC0) atomicAdd(&el[r * NH1 + h], pe[q]);
                if (wanter && r < NDST0) atomicAdd(&er[r * NH1 + h], pr[q]);
            }
        }
    }
}

// ---------------- fp32 -> fp16 conversion + el/er zero-fill fused ----------------
__global__ void convA(const float* __restrict__ f, __half* __restrict__ o,
                      float* __restrict__ el, float* __restrict__ er)
{
    size_t i = (size_t)blockIdx.x * blockDim.x + threadIdx.x;   // float4 index
    // fused zero-fill of score accumulators
    if (i < NSRC0 * NH1) el[i] = 0.f;
    if (i < NDST0 * NH1) er[i] = 0.f;
    size_t n4 = (size_t)MPAD * HD1 / 4;
    if (i >= n4) return;
    float4 v;
    if (i < (size_t)NSRC0 * HD1 / 4) v = ((const float4*)f)[i];
    else v = make_float4(0.f, 0.f, 0.f, 0.f);
    ((__half2*)o)[2 * i] = __floats2half2_rn(v.x, v.y);
    ((__half2*)o)[2 * i + 1] = __floats2half2_rn(v.z, v.w);
}
// transpose W1 [K,N] -> Bt [N,K] fp16, 32x32 smem tiles (coalesced both sides)
__global__ __launch_bounds__(256) void convB(const float* __restrict__ W, __half* __restrict__ o)
{
    __shared__ float tile[32][33];
    int kb = blockIdx.x * 32, nb = blockIdx.y * 32;
    int tx = threadIdx.x & 31, ty = threadIdx.x >> 5;   // 32 x 8
#pragma unroll
    for (int r = 0; r < 32; r += 8)
        tile[ty + r][tx] = W[(size_t)(kb + ty + r) * HD1 + nb + tx];
    __syncthreads();
#pragma unroll
    for (int r = 0; r < 32; r += 8)
        o[(size_t)(nb + ty + r) * HD1 + kb + tx] = __float2half_rn(tile[tx][ty + r]);
}

// ---------------- layer-2 SGEMM + fused scores2 ----------------
__global__ __launch_bounds__(256) void gemm2(
    const float* __restrict__ A, const float* __restrict__ B,
    float* __restrict__ C, int M,
    const float* __restrict__ al2, const float* __restrict__ ar2,
    float* __restrict__ el, float* __restrict__ er)
{
    const int BM = 128, BN = 128, BK = 8, TM = 8, TN = 8;
    const int K = ND1, N = ND2;
    __shared__ float As[BK][BM];
    __shared__ float Bs[BK][BN];

    int tid = threadIdx.x;
    int tx = tid & 15, ty = tid >> 4;
    int rowBase = blockIdx.y * BM;
    int aRow = tid >> 1, aCol = (tid & 1) * 4;
    int bRow = tid >> 5, bCol = (tid & 31) * 4;

    float acc[TM][TN];
#pragma unroll
    for (int i = 0; i < TM; i++)
#pragma unroll
        for (int j = 0; j < TN; j++) acc[i][j] = 0.f;

    for (int kt = 0; kt < K; kt += BK) {
        int gr = rowBase + aRow;
        float4 av = (gr < M) ? *(const float4*)(A + (size_t)gr * K + kt + aCol)
                             : make_float4(0.f, 0.f, 0.f, 0.f);
        As[aCol + 0][aRow] = av.x; As[aCol + 1][aRow] = av.y;
        As[aCol + 2][aRow] = av.z; As[aCol + 3][aRow] = av.w;
        float4 bv = *(const float4*)(B + (size_t)(kt + bRow) * N + bCol);
        *(float4*)&Bs[bRow][bCol] = bv;
        __syncthreads();
#pragma unroll
        for (int k = 0; k < BK; k++) {
            float ar_[TM], br_[TN];
#pragma unroll
            for (int i = 0; i < TM; i++) ar_[i] = As[k][ty * TM + i];
#pragma unroll
            for (int j = 0; j < TN; j++) br_[j] = Bs[k][tx * TN + j];
#pragma unroll
            for (int i = 0; i < TM; i++)
#pragma unroll
                for (int j = 0; j < TN; j++) acc[i][j] += ar_[i] * br_[j];
        }
        __syncthreads();
    }
#pragma unroll
    for (int i = 0; i < TM; i++) {
        int gr = rowBase + ty * TM + i;
        if (gr < M) {
            float* cp = C + (size_t)gr * N + tx * TN;
#pragma unroll
            for (int j = 0; j < TN; j += 4)
                *(float4*)(cp + j) = make_float4(acc[i][j], acc[i][j + 1], acc[i][j + 2], acc[i][j + 3]);
        }
    }

    // ---- fused scores2: half-warp (16 tx lanes) covers all 128 cols of 8 rows ----
    {
        float a2[TN], r2[TN];
#pragma unroll
        for (int j = 0; j < TN; j++) {
            a2[j] = __ldg(al2 + tx * TN + j);
            r2[j] = __ldg(ar2 + tx * TN + j);
        }
        float pl[TM], pr_[TM];
#pragma unroll
        for (int i = 0; i < TM; i++) {
            float sl = 0.f, sr = 0.f;
#pragma unroll
            for (int j = 0; j < TN; j++) { sl += acc[i][j] * a2[j]; sr += acc[i][j] * r2[j]; }
            pl[i] = sl; pr_[i] = sr;
        }
#pragma unroll
        for (int o = 1; o < 16; o <<= 1)
#pragma unroll
            for (int i = 0; i < TM; i++) {
                pl[i] += __shfl_xor_sync(0xffffffffu, pl[i], o);
                pr_[i] += __shfl_xor_sync(0xffffffffu, pr_[i], o);
            }
        if (tx == 0) {
#pragma unroll
            for (int i = 0; i < TM; i++) {
                int gr = rowBase + ty * TM + i;
                if (gr < M) el[gr] = pl[i];
                if (gr < NDST1) er[gr] = pr_[i];
            }
        }
    }
}

// ---------------- CSR build (both layers merged) ----------------
__global__ void count_edges2(const int* __restrict__ dst0, int ne0, int* __restrict__ cnt0,
                             const int* __restrict__ dst1, int ne1, int* __restrict__ cnt1) {
    int e = blockIdx.x * blockDim.x + threadIdx.x;
    if (e < ne0) atomicAdd(&cnt0[dst0[e]], 1);
    if (e < ne1) atomicAdd(&cnt1[dst1[e]], 1);
}
__global__ __launch_bounds__(1024) void scan_excl2(
    const int* __restrict__ cntA, int* __restrict__ offA, int nA,
    const int* __restrict__ cntB, int* __restrict__ offB, int nB)
{
    const int* cnt = (blockIdx.x == 0) ? cntA : cntB;
    int* off = (blockIdx.x == 0) ? offA : offB;
    int n = (blockIdx.x == 0) ? nA : nB;
    __shared__ int s[1024];
    __shared__ int stot;
    int t = threadIdx.x;
    int chunk = (n + 1023) >> 10;
    int b = t * chunk;
    int e = b + chunk; if (e > n) e = n;
    int loc = 0;
    for (int i = b; i < e; i++) loc += cnt[i];
    s[t] = loc;
    __syncthreads();
    if (t == 0) {
        int run = 0;
        for (int i = 0; i < 1024; i++) { int x = s[i]; s[i] = run; run += x; }
        stot = run;
    }
    __syncthreads();
    int run = s[t];
    for (int i = b; i < e; i++) { off[i] = run; run += cnt[i]; }
    if (t == 0) off[n] = stot;
}
__global__ void scatter_edges2(
    const int* __restrict__ src0, const int* __restrict__ dst0, int ne0,
    const int* __restrict__ off0, int* __restrict__ cur0, int* __restrict__ esrc0,
    const int* __restrict__ src1, const int* __restrict__ dst1, int ne1,
    const int* __restrict__ off1, int* __restrict__ cur1, int* __restrict__ esrc1) {
    int e = blockIdx.x * blockDim.x + threadIdx.x;
    if (e < ne0) {
        int d = dst0[e];
        esrc0[off0[d] + atomicAdd(&cur0[d], 1)] = src0[e];
    }
    if (e < ne1) {
        int d = dst1[e];
        esrc1[off1[d] + atomicAdd(&cur1[d], 1)] = src1[e];
    }
}

// ---------------- layer-1 aggregate: head-per-warp vectorized gather ----------------
__global__ __launch_bounds__(256) void aggregate1(
    const __half* __restrict__ h1, const float* __restrict__ el,
    const float* __restrict__ er, const float* __restrict__ b1,
    const int* __restrict__ off, const int* __restrict__ esrc,
    float* __restrict__ hm)
{
    int d = blockIdx.x, t = threadIdx.x;
    int wid = t >> 5, lane = t & 31;
    __shared__ float s_e[256][NH1];        // 8 KB  (edge weights, all heads)
    __shared__ int   s_src[256];
    __shared__ float s_out[NH1][ND1];      // 8 KB  (per-head relu'd outputs)

    int s0 = off[d], s1 = off[d + 1];
    float ssum = 0.f;
    float acc[8];
#pragma unroll
    for (int k = 0; k < 8; k++) acc[k] = 0.f;
    float erh[NH1];
#pragma unroll
    for (int h = 0; h < NH1; h++) erh[h] = er[d * NH1 + h];

    for (int base = s0; base < s1; base += 256) {
        int cn = s1 - base; if (cn > 256) cn = 256;
        if (t < cn) {
            int s = esrc[base + t];
            s_src[t] = s;
#pragma unroll
            for (int h = 0; h < NH1; h++) {
                float x = el[s * NH1 + h] + erh[h];
                x = (x > 0.f) ? x : 0.2f * x;   // leaky_relu(0.2)
                s_e[t][h] = __expf(x);          // shift-free: |x| small, no overflow
            }
        }
        __syncthreads();

#pragma unroll 4
        for (int j = 0; j < cn; j++) {
            float w = s_e[j][wid];              // smem broadcast
            ssum += w;
            const uint4 v = *(const uint4*)(h1 + (size_t)s_src[j] * HD1 + wid * ND1 + lane * 8);
            float2 f0 = __half22float2(*(const __half2*)&v.x);
            float2 f1 = __half22float2(*(((const __half2*)&v.x) + 1));
            float2 f2 = __half22float2(*(const __half2*)&v.z);
            float2 f3 = __half22float2(*(((const __half2*)&v.z) + 1));
            acc[0] += w * f0.x; acc[1] += w * f0.y;
            acc[2] += w * f1.x; acc[3] += w * f1.y;
            acc[4] += w * f2.x; acc[5] += w * f2.y;
            acc[6] += w * f3.x; acc[7] += w * f3.y;
        }
        __syncthreads();
    }

    // finalize this head's 8 dims: /ssum + bias, relu -> smem
    float inv = (ssum > 0.f) ? 1.f / ssum : 0.f;
#pragma unroll
    for (int k = 0; k < 8; k++) {
        float o = acc[k] * inv + b1[wid * ND1 + lane * 8 + k];
        s_out[wid][lane * 8 + k] = fmaxf(o, 0.f);
    }
    __syncthreads();

    // head mean: thread t handles dim t across all 8 heads
    float sum = 0.f;
#pragma unroll
    for (int h = 0; h < NH1; h++) sum += s_out[h][t];
    hm[(size_t)d * ND1 + t] = sum * 0.125f;
}

// ---------------- layer-2 aggregate (shift-free softmax) ----------------
__global__ __launch_bounds__(128) void aggregate2(
    const float* __restrict__ h2, const float* __restrict__ el,
    const float* __restrict__ er, const float* __restrict__ b2,
    const int* __restrict__ off, const int* __restrict__ esrc,
    float* __restrict__ out)
{
    int d = blockIdx.x, t = threadIdx.x;
    __shared__ float s_e[128];
    __shared__ int   s_src[128];

    int s0 = off[d], s1 = off[d + 1];
    float ssum = 0.f, acc = 0.f;
    float erh = er[d];

    for (int base = s0; base < s1; base += 128) {
        int cn = s1 - base; if (cn > 128) cn = 128;
        if (t < cn) {
            int s = esrc[base + t];
            s_src[t] = s;
            float x = el[s] + erh;
            x = (x > 0.f) ? x : 0.2f * x;
            s_e[t] = __expf(x);
        }
        __syncthreads();

#pragma unroll 4
        for (int j = 0; j < cn; j++) {
            float w = s_e[j];
            ssum += w;
            acc += w * h2[(size_t)s_src[j] * ND2 + t];
        }
        __syncthreads();
    }

    float o = (ssum > 0.f) ? acc / ssum : 0.f;
    out[(size_t)d * ND2 + t] = o + b2[t];
}

// ---------------- launch ----------------
extern "C" void kernel_launch(void* const* d_in, const int* in_sizes, int n_in,
                              void* d_out, int out_size)
{
    const float* feat = (const float*)d_in[0];
    const float* W1   = (const float*)d_in[1];
    const float* al1  = (const float*)d_in[2];
    const float* ar1  = (const float*)d_in[3];
    const float* b1   = (const float*)d_in[4];
    const float* W2   = (const float*)d_in[5];
    const float* al2  = (const float*)d_in[6];
    const float* ar2  = (const float*)d_in[7];
    const float* b2   = (const float*)d_in[8];
    const int* src0 = (const int*)d_in[9];
    const int* dst0 = (const int*)d_in[10];
    const int* src1 = (const int*)d_in[11];
    const int* dst1 = (const int*)d_in[12];
    float* out = (float*)d_out;

    int e0 = in_sizes[9];
    int e1 = in_sizes[11];
    int emax = (e0 > e1) ? e0 : e1;

    __half *Ahp, *Bhp, *h1p;
    float *hmp, *h2p, *el1p, *er1p, *el2p, *er2p;
    int *off1p, *cnt1p, *esrc1p, *off2p, *cnt2p, *esrc2p;
    cudaGetSymbolAddress((void**)&Ahp, g_Ah);
    cudaGetSymbolAddress((void**)&Bhp, g_Bh);
    cudaGetSymbolAddress((void**)&h1p, g_h1);
    cudaGetSymbolAddress((void**)&hmp, g_hm);
    cudaGetSymbolAddress((void**)&h2p, g_h2);
    cudaGetSymbolAddress((void**)&el1p, g_el1);
    cudaGetSymbolAddress((void**)&er1p, g_er1);
    cudaGetSymbolAddress((void**)&el2p, g_el2);
    cudaGetSymbolAddress((void**)&er2p, g_er2);
    cudaGetSymbolAddress((void**)&off1p, g_off1);
    cudaGetSymbolAddress((void**)&cnt1p, g_cnt1);
    cudaGetSymbolAddress((void**)&esrc1p, g_esrc1);
    cudaGetSymbolAddress((void**)&off2p, g_off2);
    cudaGetSymbolAddress((void**)&cnt2p, g_cnt2);
    cudaGetSymbolAddress((void**)&esrc2p, g_esrc2);

    // ---- layer 1: fp16 mma.sync GEMM + fused scores ----
    {
        size_t n4 = (size_t)MPAD * HD1 / 4;
        convA<<<(unsigned)((n4 + 255) / 256), 256>>>(feat, Ahp, el1p, er1p);
        convB<<<dim3(HD1 / 32, HD1 / 32), 256>>>(W1, Bhp);

        const int SMEM_GEMM = NSTAGE * STG;  // 96 KB
        cudaFuncSetAttribute(gemm_mma, cudaFuncAttributeMaxDynamicSharedMemorySize, SMEM_GEMM);
        dim3 grid(HD1 / GBN, MPAD / GBM);   // (16, 469)
        gemm_mma<<<grid, 256, SMEM_GEMM>>>(Ahp, Bhp, h1p, NSRC0,
                                           al1, ar1, el1p, er1p);
    }

    // ---- merged CSR build for both layers ----
    cudaMemsetAsync(cnt1p, 0, NDST0 * sizeof(int));
    cudaMemsetAsync(cnt2p, 0, NDST1 * sizeof(int));
    count_edges2<<<(emax + 255) / 256, 256>>>(dst0, e0, cnt1p, dst1, e1, cnt2p);
    scan_excl2<<<2, 1024>>>(cnt1p, off1p, NDST0, cnt2p, off2p, NDST1);
    cudaMemsetAsync(cnt1p, 0, NDST0 * sizeof(int));
    cudaMemsetAsync(cnt2p, 0, NDST1 * sizeof(int));
    scatter_edges2<<<(emax + 255) / 256, 256>>>(src0, dst0, e0, off1p, cnt1p, esrc1p,
                                                src1, dst1, e1, off2p, cnt2p, esrc2p);

    aggregate1<<<NDST0, 256>>>(h1p, el1p, er1p, b1, off1p, esrc1p, hmp);

    // ---- layer 2: SGEMM + fused scores2 ----
    {
        dim3 grid(1, (NDST0 + 127) / 128);
        gemm2<<<grid, 256>>>(hmp, W2, h2p, NDST0, al2, ar2, el2p, er2p);
    }

    aggregate2<<<NDST1, 128>>>(h2p, el2p, er2p, b2, off2p, esrc2p, out);
}

// round 15
// speedup vs baseline: 1.2024x; 1.0132x over previous
#include <cuda_runtime.h>
#include <cuda_fp16.h>
#include <cstdint>

// ---------------- problem constants ----------------
#define NSRC0 60000
#define MPAD  60032    // 469 * 128
#define NDST0 15000
#define NDST1 4000
#define NH1   8
#define ND1   256
#define ND2   128
#define HD1   2048   // NH1*ND1 (also IN_DIM)
#define E0MAX 240000
#define E1MAX 64000

// ---------------- device scratch (static, allowed) ----------------
__device__ __half g_Ah[(size_t)MPAD * HD1];          // 246 MB (fp16 feat)
__device__ __half g_Bh[(size_t)HD1 * HD1];           // 8.4 MB (transposed W1: [N,K], fp16)
__device__ __half g_h1[(size_t)NSRC0 * HD1];         // 246 MB (fp16 h1)
__device__ float g_el1[NSRC0 * NH1];
__device__ float g_er1[NDST0 * NH1];
__device__ int   g_off1[NDST0 + 1];
__device__ int   g_cnt1[NDST0];
__device__ int   g_esrc1[E0MAX];
__device__ float g_hm[(size_t)NDST0 * ND1];
__device__ float g_h2[(size_t)NDST0 * ND2];
__device__ float g_el2[NDST0];
__device__ float g_er2[NDST1];
__device__ int   g_off2[NDST1 + 1];
__device__ int   g_cnt2[NDST1];
__device__ int   g_esrc2[E1MAX];

// =====================================================================
// mma.sync fp16 GEMM: C[M,2048] = A @ B^T (fp16 out).  Bt is [N,K].
// CTA 128x128, BK=64, 3-stage cp.async, 256 threads, warp tile 32x64,
// __launch_bounds__(256,2) -> 128 regs, 2 CTAs/SM (2x96KB smem).
// ONE __syncthreads per mainloop iter (CUTLASS multistage ordering).
// Fused epilogue: el/er attention-score partials via atomicAdd.
// =====================================================================
static __device__ __forceinline__ void cp16(uint32_t s, const void* g) {
    asm volatile("cp.async.cg.shared.global [%0], [%1], 16;" :: "r"(s), "l"(g));
}
static __device__ __forceinline__ void ldsm4(uint32_t* r, uint32_t addr) {
    asm volatile("ldmatrix.sync.aligned.m8n8.x4.shared.b16 {%0,%1,%2,%3}, [%4];"
                 : "=r"(r[0]), "=r"(r[1]), "=r"(r[2]), "=r"(r[3]) : "r"(addr));
}
static __device__ __forceinline__ void mma16816(float* d, const uint32_t* a, const uint32_t* b) {
    asm volatile(
        "mma.sync.aligned.m16n8k16.row.col.f32.f16.f16.f32 "
        "{%0,%1,%2,%3}, {%4,%5,%6,%7}, {%8,%9}, {%0,%1,%2,%3};"
        : "+f"(d[0]), "+f"(d[1]), "+f"(d[2]), "+f"(d[3])
        : "r"(a[0]), "r"(a[1]), "r"(a[2]), "r"(a[3]), "r"(b[0]), "r"(b[1]));
}

#define GBM 128
#define GBN 128
#define GBK 64
#define KCH (HD1 / GBK)        // 32
#define STG 32768              // A 16KB + B 16KB per stage (128 rows x 128B)
#define NSTAGE 3

__global__ __launch_bounds__(256, 2) void gemm_mma(
    const __half* __restrict__ Ah, const __half* __restrict__ Bh,
    __half* __restrict__ C, int M,
    const float* __restrict__ al1, const float* __restrict__ ar1,
    float* __restrict__ el, float* __restrict__ er)
{
    extern __shared__ __align__(128) char smem[];
    uint32_t sbase = (uint32_t)__cvta_generic_to_shared(smem);

    int tid = threadIdx.x, wid = tid >> 5, lane = tid & 31;
    int mrow = blockIdx.y * GBM;
    int ncol = blockIdx.x * GBN;
    int wm = (wid & 3) * 32;       // warp row base in tile
    int wn = (wid >> 2) * 64;      // warp col base in tile

    float acc[2][8][4];
#pragma unroll
    for (int i = 0; i < 2; i++)
#pragma unroll
        for (int j = 0; j < 8; j++)
#pragma unroll
            for (int q = 0; q < 4; q++) acc[i][j][q] = 0.f;

    auto stage_load = [&](int it, int s) {
        uint32_t st = sbase + (uint32_t)s * STG;
        int kb = it * GBK;
#pragma unroll
        for (int u = 0; u < 4; u++) {
            int idx = tid + u * 256;
            int r = idx >> 3, c = idx & 7;
            uint32_t so = ((uint32_t)r << 7) | ((uint32_t)((c ^ (r & 7))) << 4);
            cp16(st + so, Ah + (size_t)(mrow + r) * HD1 + kb + c * 8);
            cp16(st + 16384u + so, Bh + (size_t)(ncol + r) * HD1 + kb + c * 8);
        }
        asm volatile("cp.async.commit_group;");
    };

    auto compute = [&](int s) {
        uint32_t sA = sbase + (uint32_t)s * STG;
        uint32_t sB = sA + 16384u;
#pragma unroll
        for (int ks = 0; ks < 4; ks++) {
            uint32_t a[2][4];
#pragma unroll
            for (int mr = 0; mr < 2; mr++) {
                int row = wm + mr * 16 + (lane & 15);
                int ch = ks * 2 + (lane >> 4);
                ldsm4(a[mr], sA + ((uint32_t)row << 7) + ((uint32_t)((ch ^ (row & 7))) << 4));
            }
            uint32_t b[4][4];
#pragma unroll
            for (int nb = 0; nb < 4; nb++) {
                int n = wn + nb * 16 + (lane & 7) + ((lane >> 4) << 3);
                int ch = ks * 2 + ((lane >> 3) & 1);
                ldsm4(b[nb], sB + ((uint32_t)n << 7) + ((uint32_t)((ch ^ (n & 7))) << 4));
            }
#pragma unroll
            for (int mr = 0; mr < 2; mr++)
#pragma unroll
                for (int nb = 0; nb < 4; nb++)
#pragma unroll
                    for (int hf = 0; hf < 2; hf++)
                        mma16816(acc[mr][nb * 2 + hf], a[mr], &b[nb][hf * 2]);
        }
    };

    stage_load(0, 0);
    stage_load(1, 1);
    for (int it = 0; it < KCH; it++) {
        if (it < KCH - 1) {
            asm volatile("cp.async.wait_group 1;" ::: "memory");
        } else {
            asm volatile("cp.async.wait_group 0;" ::: "memory");
        }
        __syncthreads();
        if (it + 2 < KCH) stage_load(it + 2, (it + 2) % NSTAGE);
        compute(it % NSTAGE);
    }

    // ---- store C (fp16) ----
#pragma unroll
    for (int mr = 0; mr < 2; mr++)
#pragma unroll
        for (int n8 = 0; n8 < 8; n8++) {
            int row = mrow + wm + mr * 16 + (lane >> 2);
            int col = ncol + wn + n8 * 8 + (lane & 3) * 2;
            float* d = acc[mr][n8];
            if (row < M)
                *(__half2*)(C + (size_t)row * HD1 + col) = __floats2half2_rn(d[0], d[1]);
            if (row + 8 < M)
                *(__half2*)(C + (size_t)(row + 8) * HD1 + col) = __floats2half2_rn(d[2], d[3]);
        }

    // ---- fused attention-score partials: el[n,h] += h.al, er[n,h] += h.ar ----
    {
        int h = ncol >> 8;                       // head index (ncol / 256)
        int cb = (ncol & 255) + wn + (lane & 3) * 2;   // within-head col of d[0]
        float2 alv[8], arv[8];
        bool wanter = (mrow < NDST0);
#pragma unroll
        for (int n8 = 0; n8 < 8; n8++) {
            int cc = h * ND1 + cb + n8 * 8;
            alv[n8] = make_float2(__ldg(al1 + cc), __ldg(al1 + cc + 1));
            if (wanter) arv[n8] = make_float2(__ldg(ar1 + cc), __ldg(ar1 + cc + 1));
        }
        float pe[4] = {0.f, 0.f, 0.f, 0.f};
        float pr[4] = {0.f, 0.f, 0.f, 0.f};
#pragma unroll
        for (int mr = 0; mr < 2; mr++)
#pragma unroll
            for (int n8 = 0; n8 < 8; n8++) {
                float* d = acc[mr][n8];
                pe[mr * 2 + 0] += d[0] * alv[n8].x + d[1] * alv[n8].y;
                pe[mr * 2 + 1] += d[2] * alv[n8].x + d[3] * alv[n8].y;
                if (wanter) {
                    pr[mr * 2 + 0] += d[0] * arv[n8].x + d[1] * arv[n8].y;
                    pr[mr * 2 + 1] += d[2] * arv[n8].x + d[3] * arv[n8].y;
                }
            }
#pragma unroll
        for (int q = 0; q < 4; q++) {
            pe[q] += __shfl_xor_sync(0xffffffffu, pe[q], 1);
            pe[q] += __shfl_xor_sync(0xffffffffu, pe[q], 2);
            pr[q] += __shfl_xor_sync(0xffffffffu, pr[q], 1);
            pr[q] += __shfl_xor_sync(0xffffffffu, pr[q], 2);
        }
        if ((lane & 3) == 0) {
            int rbase = mrow + wm + (lane >> 2);
#pragma unroll
            for (int q = 0; q < 4; q++) {
                int r = rbase + (q & 1) * 8 + (q >> 1) * 16;
                if (r < NSRC0) atomicAdd(&el[r * NH1 + h], pe[q]);
                if (wanter && r < NDST0) atomicAdd(&er[r * NH1 + h], pr[q]);
            }
        }
    }
}

// ---------------- fp32 -> fp16 conversion + el/er zero-fill fused ----------------
__global__ void convA(const float* __restrict__ f, __half* __restrict__ o,
                      float* __restrict__ el, float* __restrict__ er)
{
    size_t i = (size_t)blockIdx.x * blockDim.x + threadIdx.x;   // float4 index
    if (i < NSRC0 * NH1) el[i] = 0.f;
    if (i < NDST0 * NH1) er[i] = 0.f;
    size_t n4 = (size_t)MPAD * HD1 / 4;
    if (i >= n4) return;
    float4 v;
    if (i < (size_t)NSRC0 * HD1 / 4) v = ((const float4*)f)[i];
    else v = make_float4(0.f, 0.f, 0.f, 0.f);
    ((__half2*)o)[2 * i] = __floats2half2_rn(v.x, v.y);
    ((__half2*)o)[2 * i + 1] = __floats2half2_rn(v.z, v.w);
}
// transpose W1 [K,N] -> Bt [N,K] fp16, 32x32 smem tiles (coalesced both sides)
__global__ __launch_bounds__(256) void convB(const float* __restrict__ W, __half* __restrict__ o)
{
    __shared__ float tile[32][33];
    int kb = blockIdx.x * 32, nb = blockIdx.y * 32;
    int tx = threadIdx.x & 31, ty = threadIdx.x >> 5;   // 32 x 8
#pragma unroll
    for (int r = 0; r < 32; r += 8)
        tile[ty + r][tx] = W[(size_t)(kb + ty + r) * HD1 + nb + tx];
    __syncthreads();
#pragma unroll
    for (int r = 0; r < 32; r += 8)
        o[(size_t)(nb + ty + r) * HD1 + kb + tx] = __float2half_rn(tile[tx][ty + r]);
}

// ---------------- layer-2 SGEMM + fused scores2 ----------------
__global__ __launch_bounds__(256) void gemm2(
    const float* __restrict__ A, const float* __restrict__ B,
    float* __restrict__ C, int M,
    const float* __restrict__ al2, const float* __restrict__ ar2,
    float* __restrict__ el, float* __restrict__ er)
{
    const int BM = 128, BN = 128, BK = 8, TM = 8, TN = 8;
    const int K = ND1, N = ND2;
    __shared__ float As[BK][BM];
    __shared__ float Bs[BK][BN];

    int tid = threadIdx.x;
    int tx = tid & 15, ty = tid >> 4;
    int rowBase = blockIdx.y * BM;
    int aRow = tid >> 1, aCol = (tid & 1) * 4;
    int bRow = tid >> 5, bCol = (tid & 31) * 4;

    float acc[TM][TN];
#pragma unroll
    for (int i = 0; i < TM; i++)
#pragma unroll
        for (int j = 0; j < TN; j++) acc[i][j] = 0.f;

    for (int kt = 0; kt < K; kt += BK) {
        int gr = rowBase + aRow;
        float4 av = (gr < M) ? *(const float4*)(A + (size_t)gr * K + kt + aCol)
                             : make_float4(0.f, 0.f, 0.f, 0.f);
        As[aCol + 0][aRow] = av.x; As[aCol + 1][aRow] = av.y;
        As[aCol + 2][aRow] = av.z; As[aCol + 3][aRow] = av.w;
        float4 bv = *(const float4*)(B + (size_t)(kt + bRow) * N + bCol);
        *(float4*)&Bs[bRow][bCol] = bv;
        __syncthreads();
#pragma unroll
        for (int k = 0; k < BK; k++) {
            float ar_[TM], br_[TN];
#pragma unroll
            for (int i = 0; i < TM; i++) ar_[i] = As[k][ty * TM + i];
#pragma unroll
            for (int j = 0; j < TN; j++) br_[j] = Bs[k][tx * TN + j];
#pragma unroll
            for (int i = 0; i < TM; i++)
#pragma unroll
                for (int j = 0; j < TN; j++) acc[i][j] += ar_[i] * br_[j];
        }
        __syncthreads();
    }
#pragma unroll
    for (int i = 0; i < TM; i++) {
        int gr = rowBase + ty * TM + i;
        if (gr < M) {
            float* cp = C + (size_t)gr * N + tx * TN;
#pragma unroll
            for (int j = 0; j < TN; j += 4)
                *(float4*)(cp + j) = make_float4(acc[i][j], acc[i][j + 1], acc[i][j + 2], acc[i][j + 3]);
        }
    }

    // ---- fused scores2: half-warp (16 tx lanes) covers all 128 cols of 8 rows ----
    {
        float a2[TN], r2[TN];
#pragma unroll
        for (int j = 0; j < TN; j++) {
            a2[j] = __ldg(al2 + tx * TN + j);
            r2[j] = __ldg(ar2 + tx * TN + j);
        }
        float pl[TM], pr_[TM];
#pragma unroll
        for (int i = 0; i < TM; i++) {
            float sl = 0.f, sr = 0.f;
#pragma unroll
            for (int j = 0; j < TN; j++) { sl += acc[i][j] * a2[j]; sr += acc[i][j] * r2[j]; }
            pl[i] = sl; pr_[i] = sr;
        }
#pragma unroll
        for (int o = 1; o < 16; o <<= 1)
#pragma unroll
            for (int i = 0; i < TM; i++) {
                pl[i] += __shfl_xor_sync(0xffffffffu, pl[i], o);
                pr_[i] += __shfl_xor_sync(0xffffffffu, pr_[i], o);
            }
        if (tx == 0) {
#pragma unroll
            for (int i = 0; i < TM; i++) {
                int gr = rowBase + ty * TM + i;
                if (gr < M) el[gr] = pl[i];
                if (gr < NDST1) er[gr] = pr_[i];
            }
        }
    }
}

// ---------------- CSR build (both layers merged) ----------------
__global__ void count_edges2(const int* __restrict__ dst0, int ne0, int* __restrict__ cnt0,
                             const int* __restrict__ dst1, int ne1, int* __restrict__ cnt1) {
    int e = blockIdx.x * blockDim.x + threadIdx.x;
    if (e < ne0) atomicAdd(&cnt0[dst0[e]], 1);
    if (e < ne1) atomicAdd(&cnt1[dst1[e]], 1);
}
__global__ __launch_bounds__(1024) void scan_excl2(
    const int* __restrict__ cntA, int* __restrict__ offA, int nA,
    const int* __restrict__ cntB, int* __restrict__ offB, int nB)
{
    const int* cnt = (blockIdx.x == 0) ? cntA : cntB;
    int* off = (blockIdx.x == 0) ? offA : offB;
    int n = (blockIdx.x == 0) ? nA : nB;
    __shared__ int s[1024];
    __shared__ int stot;
    int t = threadIdx.x;
    int chunk = (n + 1023) >> 10;
    int b = t * chunk;
    int e = b + chunk; if (e > n) e = n;
    int loc = 0;
    for (int i = b; i < e; i++) loc += cnt[i];
    s[t] = loc;
    __syncthreads();
    if (t == 0) {
        int run = 0;
        for (int i = 0; i < 1024; i++) { int x = s[i]; s[i] = run; run += x; }
        stot = run;
    }
    __syncthreads();
    int run = s[t];
    for (int i = b; i < e; i++) { off[i] = run; run += cnt[i]; }
    if (t == 0) off[n] = stot;
}
__global__ void scatter_edges2(
    const int* __restrict__ src0, const int* __restrict__ dst0, int ne0,
    const int* __restrict__ off0, int* __restrict__ cur0, int* __restrict__ esrc0,
    const int* __restrict__ src1, const int* __restrict__ dst1, int ne1,
    const int* __restrict__ off1, int* __restrict__ cur1, int* __restrict__ esrc1) {
    int e = blockIdx.x * blockDim.x + threadIdx.x;
    if (e < ne0) {
        int d = dst0[e];
        esrc0[off0[d] + atomicAdd(&cur0[d], 1)] = src0[e];
    }
    if (e < ne1) {
        int d = dst1[e];
        esrc1[off1[d] + atomicAdd(&cur1[d], 1)] = src1[e];
    }
}

// ---------------- layer-1 aggregate: head-per-warp vectorized gather ----------------
__global__ __launch_bounds__(256) void aggregate1(
    const __half* __restrict__ h1, const float* __restrict__ el,
    const float* __restrict__ er, const float* __restrict__ b1,
    const int* __restrict__ off, const int* __restrict__ esrc,
    float* __restrict__ hm)
{
    int d = blockIdx.x, t = threadIdx.x;
    int wid = t >> 5, lane = t & 31;
    __shared__ float s_e[256][NH1];
    __shared__ int   s_src[256];
    __shared__ float s_out[NH1][ND1];

    int s0 = off[d], s1 = off[d + 1];
    float ssum = 0.f;
    float acc[8];
#pragma unroll
    for (int k = 0; k < 8; k++) acc[k] = 0.f;
    float erh[NH1];
#pragma unroll
    for (int h = 0; h < NH1; h++) erh[h] = er[d * NH1 + h];

    for (int base = s0; base < s1; base += 256) {
        int cn = s1 - base; if (cn > 256) cn = 256;
        if (t < cn) {
            int s = esrc[base + t];
            s_src[t] = s;
#pragma unroll
            for (int h = 0; h < NH1; h++) {
                float x = el[s * NH1 + h] + erh[h];
                x = (x > 0.f) ? x : 0.2f * x;   // leaky_relu(0.2)
                s_e[t][h] = __expf(x);          // shift-free: |x| small, no overflow
            }
        }
        __syncthreads();

#pragma unroll 4
        for (int j = 0; j < cn; j++) {
            float w = s_e[j][wid];
            ssum += w;
            const uint4 v = *(const uint4*)(h1 + (size_t)s_src[j] * HD1 + wid * ND1 + lane * 8);
            float2 f0 = __half22float2(*(const __half2*)&v.x);
            float2 f1 = __half22float2(*(((const __half2*)&v.x) + 1));
            float2 f2 = __half22float2(*(const __half2*)&v.z);
            float2 f3 = __half22float2(*(((const __half2*)&v.z) + 1));
            acc[0] += w * f0.x; acc[1] += w * f0.y;
            acc[2] += w * f1.x; acc[3] += w * f1.y;
            acc[4] += w * f2.x; acc[5] += w * f2.y;
            acc[6] += w * f3.x; acc[7] += w * f3.y;
        }
        __syncthreads();
    }

    float inv = (ssum > 0.f) ? 1.f / ssum : 0.f;
#pragma unroll
    for (int k = 0; k < 8; k++) {
        float o = acc[k] * inv + b1[wid * ND1 + lane * 8 + k];
        s_out[wid][lane * 8 + k] = fmaxf(o, 0.f);
    }
    __syncthreads();

    float sum = 0.f;
#pragma unroll
    for (int h = 0; h < NH1; h++) sum += s_out[h][t];
    hm[(size_t)d * ND1 + t] = sum * 0.125f;
}

// ---------------- layer-2 aggregate (shift-free softmax) ----------------
__global__ __launch_bounds__(128) void aggregate2(
    const float* __restrict__ h2, const float* __restrict__ el,
    const float* __restrict__ er, const float* __restrict__ b2,
    const int* __restrict__ off, const int* __restrict__ esrc,
    float* __restrict__ out)
{
    int d = blockIdx.x, t = threadIdx.x;
    __shared__ float s_e[128];
    __shared__ int   s_src[128];

    int s0 = off[d], s1 = off[d + 1];
    float ssum = 0.f, acc = 0.f;
    float erh = er[d];

    for (int base = s0; base < s1; base += 128) {
        int cn = s1 - base; if (cn > 128) cn = 128;
        if (t < cn) {
            int s = esrc[base + t];
            s_src[t] = s;
            float x = el[s] + erh;
            x = (x > 0.f) ? x : 0.2f * x;
            s_e[t] = __expf(x);
        }
        __syncthreads();

#pragma unroll 4
        for (int j = 0; j < cn; j++) {
            float w = s_e[j];
            ssum += w;
            acc += w * h2[(size_t)s_src[j] * ND2 + t];
        }
        __syncthreads();
    }

    float o = (ssum > 0.f) ? acc / ssum : 0.f;
    out[(size_t)d * ND2 + t] = o + b2[t];
}

// ---------------- launch ----------------
extern "C" void kernel_launch(void* const* d_in, const int* in_sizes, int n_in,
                              void* d_out, int out_size)
{
    const float* feat = (const float*)d_in[0];
    const float* W1   = (const float*)d_in[1];
    const float* al1  = (const float*)d_in[2];
    const float* ar1  = (const float*)d_in[3];
    const float* b1   = (const float*)d_in[4];
    const float* W2   = (const float*)d_in[5];
    const float* al2  = (const float*)d_in[6];
    const float* ar2  = (const float*)d_in[7];
    const float* b2   = (const float*)d_in[8];
    const int* src0 = (const int*)d_in[9];
    const int* dst0 = (const int*)d_in[10];
    const int* src1 = (const int*)d_in[11];
    const int* dst1 = (const int*)d_in[12];
    float* out = (float*)d_out;

    int e0 = in_sizes[9];
    int e1 = in_sizes[11];
    int emax = (e0 > e1) ? e0 : e1;

    __half *Ahp, *Bhp, *h1p;
    float *hmp, *h2p, *el1p, *er1p, *el2p, *er2p;
    int *off1p, *cnt1p, *esrc1p, *off2p, *cnt2p, *esrc2p;
    cudaGetSymbolAddress((void**)&Ahp, g_Ah);
    cudaGetSymbolAddress((void**)&Bhp, g_Bh);
    cudaGetSymbolAddress((void**)&h1p, g_h1);
    cudaGetSymbolAddress((void**)&hmp, g_hm);
    cudaGetSymbolAddress((void**)&h2p, g_h2);
    cudaGetSymbolAddress((void**)&el1p, g_el1);
    cudaGetSymbolAddress((void**)&er1p, g_er1);
    cudaGetSymbolAddress((void**)&el2p, g_el2);
    cudaGetSymbolAddress((void**)&er2p, g_er2);
    cudaGetSymbolAddress((void**)&off1p, g_off1);
    cudaGetSymbolAddress((void**)&cnt1p, g_cnt1);
    cudaGetSymbolAddress((void**)&esrc1p, g_esrc1);
    cudaGetSymbolAddress((void**)&off2p, g_off2);
    cudaGetSymbolAddress((void**)&cnt2p, g_cnt2);
    cudaGetSymbolAddress((void**)&esrc2p, g_esrc2);

    // ---- side stream: convB + CSR build run concurrent with convA+GEMM ----
    cudaStream_t s2;
    cudaStreamCreateWithFlags(&s2, cudaStreamNonBlocking);
    cudaEvent_t evFork, evB, evCSR;
    cudaEventCreateWithFlags(&evFork, cudaEventDisableTiming);
    cudaEventCreateWithFlags(&evB, cudaEventDisableTiming);
    cudaEventCreateWithFlags(&evCSR, cudaEventDisableTiming);

    cudaEventRecord(evFork, 0);
    cudaStreamWaitEvent(s2, evFork, 0);

    // side stream work
    convB<<<dim3(HD1 / 32, HD1 / 32), 256, 0, s2>>>(W1, Bhp);
    cudaEventRecord(evB, s2);
    cudaMemsetAsync(cnt1p, 0, NDST0 * sizeof(int), s2);
    cudaMemsetAsync(cnt2p, 0, NDST1 * sizeof(int), s2);
    count_edges2<<<(emax + 255) / 256, 256, 0, s2>>>(dst0, e0, cnt1p, dst1, e1, cnt2p);
    scan_excl2<<<2, 1024, 0, s2>>>(cnt1p, off1p, NDST0, cnt2p, off2p, NDST1);
    cudaMemsetAsync(cnt1p, 0, NDST0 * sizeof(int), s2);
    cudaMemsetAsync(cnt2p, 0, NDST1 * sizeof(int), s2);
    scatter_edges2<<<(emax + 255) / 256, 256, 0, s2>>>(src0, dst0, e0, off1p, cnt1p, esrc1p,
                                                       src1, dst1, e1, off2p, cnt2p, esrc2p);
    cudaEventRecord(evCSR, s2);

    // main stream: convA -> (needs convB) gemm -> (needs CSR) aggregate1 -> ...
    {
        size_t n4 = (size_t)MPAD * HD1 / 4;
        convA<<<(unsigned)((n4 + 255) / 256), 256>>>(feat, Ahp, el1p, er1p);

        cudaStreamWaitEvent(0, evB, 0);
        const int SMEM_GEMM = NSTAGE * STG;  // 96 KB
        cudaFuncSetAttribute(gemm_mma, cudaFuncAttributeMaxDynamicSharedMemorySize, SMEM_GEMM);
        dim3 grid(HD1 / GBN, MPAD / GBM);   // (16, 469)
        gemm_mma<<<grid, 256, SMEM_GEMM>>>(Ahp, Bhp, h1p, NSRC0,
                                           al1, ar1, el1p, er1p);
    }

    cudaStreamWaitEvent(0, evCSR, 0);
    aggregate1<<<NDST0, 256>>>(h1p, el1p, er1p, b1, off1p, esrc1p, hmp);

    {
        dim3 grid(1, (NDST0 + 127) / 128);
        gemm2<<<grid, 256>>>(hmp, W2, h2p, NDST0, al2, ar2, el2p, er2p);
    }

    aggregate2<<<NDST1, 128>>>(h2p, el2p, er2p, b2, off2p, esrc2p, out);

    // release host-side resources (no device memory involved)
    cudaEventDestroy(evFork);
    cudaEventDestroy(evB);
    cudaEventDestroy(evCSR);
    cudaStreamDestroy(s2);
}

// round 16
// speedup vs baseline: 1.2163x; 1.0116x over previous
#include <cuda_runtime.h>
#include <cuda_fp16.h>
#include <cstdint>

// ---------------- problem constants ----------------
#define NSRC0 60000
#define MPAD  60032    // 469 * 128
#define NDST0 15000
#define NDST1 4000
#define NH1   8
#define ND1   256
#define ND2   128
#define HD1   2048   // NH1*ND1 (also IN_DIM)
#define E0MAX 240000
#define E1MAX 64000

// GEMM row-chunking (blockIdx.y bands)
#define YCH0 235
#define YCH1 234   // YCH0+YCH1 = 469 = MPAD/128

// ---------------- device scratch (static, allowed) ----------------
__device__ __half g_Ah[(size_t)MPAD * HD1];          // 246 MB (fp16 feat)
__device__ __half g_Bh[(size_t)HD1 * HD1];           // 8.4 MB (transposed W1: [N,K], fp16)
__device__ __half g_h1[(size_t)NSRC0 * HD1];         // 246 MB (fp16 h1)
__device__ float g_el1[NSRC0 * NH1];
__device__ float g_er1[NDST0 * NH1];
__device__ int   g_off1[NDST0 + 1];
__device__ int   g_cnt1[NDST0];
__device__ int   g_esrc1[E0MAX];
__device__ float g_hm[(size_t)NDST0 * ND1];
__device__ float g_h2[(size_t)NDST0 * ND2];
__device__ float g_el2[NDST0];
__device__ float g_er2[NDST1];
__device__ int   g_off2[NDST1 + 1];
__device__ int   g_cnt2[NDST1];
__device__ int   g_esrc2[E1MAX];

// =====================================================================
// mma.sync fp16 GEMM: C[M,2048] = A @ B^T (fp16 out).  Bt is [N,K].
// CTA 128x128, BK=64, 3-stage cp.async, 256 threads, warp tile 32x64,
// __launch_bounds__(256,2) -> 128 regs, 2 CTAs/SM (2x96KB smem).
// ONE __syncthreads per mainloop iter (CUTLASS multistage ordering).
// y0: row-band offset (chunked launch for convA overlap).
// Fused epilogue: el/er attention-score partials via atomicAdd.
// =====================================================================
static __device__ __forceinline__ void cp16(uint32_t s, const void* g) {
    asm volatile("cp.async.cg.shared.global [%0], [%1], 16;" :: "r"(s), "l"(g));
}
static __device__ __forceinline__ void ldsm4(uint32_t* r, uint32_t addr) {
    asm volatile("ldmatrix.sync.aligned.m8n8.x4.shared.b16 {%0,%1,%2,%3}, [%4];"
                 : "=r"(r[0]), "=r"(r[1]), "=r"(r[2]), "=r"(r[3]) : "r"(addr));
}
static __device__ __forceinline__ void mma16816(float* d, const uint32_t* a, const uint32_t* b) {
    asm volatile(
        "mma.sync.aligned.m16n8k16.row.col.f32.f16.f16.f32 "
        "{%0,%1,%2,%3}, {%4,%5,%6,%7}, {%8,%9}, {%0,%1,%2,%3};"
        : "+f"(d[0]), "+f"(d[1]), "+f"(d[2]), "+f"(d[3])
        : "r"(a[0]), "r"(a[1]), "r"(a[2]), "r"(a[3]), "r"(b[0]), "r"(b[1]));
}

#define GBM 128
#define GBN 128
#define GBK 64
#define KCH (HD1 / GBK)        // 32
#define STG 32768              // A 16KB + B 16KB per stage (128 rows x 128B)
#define NSTAGE 3

__global__ __launch_bounds__(256, 2) void gemm_mma(
    const __half* __restrict__ Ah, const __half* __restrict__ Bh,
    __half* __restrict__ C, int M, int y0,
    const float* __restrict__ al1, const float* __restrict__ ar1,
    float* __restrict__ el, float* __restrict__ er)
{
    extern __shared__ __align__(128) char smem[];
    uint32_t sbase = (uint32_t)__cvta_generic_to_shared(smem);

    int tid = threadIdx.x, wid = tid >> 5, lane = tid & 31;
    int mrow = (blockIdx.y + y0) * GBM;
    int ncol = blockIdx.x * GBN;
    int wm = (wid & 3) * 32;       // warp row base in tile
    int wn = (wid >> 2) * 64;      // warp col base in tile

    float acc[2][8][4];
#pragma unroll
    for (int i = 0; i < 2; i++)
#pragma unroll
        for (int j = 0; j < 8; j++)
#pragma unroll
            for (int q = 0; q < 4; q++) acc[i][j][q] = 0.f;

    auto stage_load = [&](int it, int s) {
        uint32_t st = sbase + (uint32_t)s * STG;
        int kb = it * GBK;
#pragma unroll
        for (int u = 0; u < 4; u++) {
            int idx = tid + u * 256;
            int r = idx >> 3, c = idx & 7;
            uint32_t so = ((uint32_t)r << 7) | ((uint32_t)((c ^ (r & 7))) << 4);
            cp16(st + so, Ah + (size_t)(mrow + r) * HD1 + kb + c * 8);
            cp16(st + 16384u + so, Bh + (size_t)(ncol + r) * HD1 + kb + c * 8);
        }
        asm volatile("cp.async.commit_group;");
    };

    auto compute = [&](int s) {
        uint32_t sA = sbase + (uint32_t)s * STG;
        uint32_t sB = sA + 16384u;
#pragma unroll
        for (int ks = 0; ks < 4; ks++) {
            uint32_t a[2][4];
#pragma unroll
            for (int mr = 0; mr < 2; mr++) {
                int row = wm + mr * 16 + (lane & 15);
                int ch = ks * 2 + (lane >> 4);
                ldsm4(a[mr], sA + ((uint32_t)row << 7) + ((uint32_t)((ch ^ (row & 7))) << 4));
            }
            uint32_t b[4][4];
#pragma unroll
            for (int nb = 0; nb < 4; nb++) {
                int n = wn + nb * 16 + (lane & 7) + ((lane >> 4) << 3);
                int ch = ks * 2 + ((lane >> 3) & 1);
                ldsm4(b[nb], sB + ((uint32_t)n << 7) + ((uint32_t)((ch ^ (n & 7))) << 4));
            }
#pragma unroll
            for (int mr = 0; mr < 2; mr++)
#pragma unroll
                for (int nb = 0; nb < 4; nb++)
#pragma unroll
                    for (int hf = 0; hf < 2; hf++)
                        mma16816(acc[mr][nb * 2 + hf], a[mr], &b[nb][hf * 2]);
        }
    };

    stage_load(0, 0);
    stage_load(1, 1);
    for (int it = 0; it < KCH; it++) {
        if (it < KCH - 1) {
            asm volatile("cp.async.wait_group 1;" ::: "memory");
        } else {
            asm volatile("cp.async.wait_group 0;" ::: "memory");
        }
        __syncthreads();
        if (it + 2 < KCH) stage_load(it + 2, (it + 2) % NSTAGE);
        compute(it % NSTAGE);
    }

    // ---- store C (fp16) ----
#pragma unroll
    for (int mr = 0; mr < 2; mr++)
#pragma unroll
        for (int n8 = 0; n8 < 8; n8++) {
            int row = mrow + wm + mr * 16 + (lane >> 2);
            int col = ncol + wn + n8 * 8 + (lane & 3) * 2;
            float* d = acc[mr][n8];
            if (row < M)
                *(__half2*)(C + (size_t)row * HD1 + col) = __floats2half2_rn(d[0], d[1]);
            if (row + 8 < M)
                *(__half2*)(C + (size_t)(row + 8) * HD1 + col) = __floats2half2_rn(d[2], d[3]);
        }

    // ---- fused attention-score partials: el[n,h] += h.al, er[n,h] += h.ar ----
    {
        int h = ncol >> 8;                       // head index (ncol / 256)
        int cb = (ncol & 255) + wn + (lane & 3) * 2;   // within-head col of d[0]
        float2 alv[8], arv[8];
        bool wanter = (mrow < NDST0);
#pragma unroll
        for (int n8 = 0; n8 < 8; n8++) {
            int cc = h * ND1 + cb + n8 * 8;
            alv[n8] = make_float2(__ldg(al1 + cc), __ldg(al1 + cc + 1));
            if (wanter) arv[n8] = make_float2(__ldg(ar1 + cc), __ldg(ar1 + cc + 1));
        }
        float pe[4] = {0.f, 0.f, 0.f, 0.f};
        float pr[4] = {0.f, 0.f, 0.f, 0.f};
#pragma unroll
        for (int mr = 0; mr < 2; mr++)
#pragma unroll
            for (int n8 = 0; n8 < 8; n8++) {
                float* d = acc[mr][n8];
                pe[mr * 2 + 0] += d[0] * alv[n8].x + d[1] * alv[n8].y;
                pe[mr * 2 + 1] += d[2] * alv[n8].x + d[3] * alv[n8].y;
                if (wanter) {
                    pr[mr * 2 + 0] += d[0] * arv[n8].x + d[1] * arv[n8].y;
                    pr[mr * 2 + 1] += d[2] * arv[n8].x + d[3] * arv[n8].y;
                }
            }
#pragma unroll
        for (int q = 0; q < 4; q++) {
            pe[q] += __shfl_xor_sync(0xffffffffu, pe[q], 1);
            pe[q] += __shfl_xor_sync(0xffffffffu, pe[q], 2);
            pr[q] += __shfl_xor_sync(0xffffffffu, pr[q], 1);
            pr[q] += __shfl_xor_sync(0xffffffffu, pr[q], 2);
        }
        if ((lane & 3) == 0) {
            int rbase = mrow + wm + (lane >> 2);
#pragma unroll
            for (int q = 0; q < 4; q++) {
                int r = rbase + (q & 1) * 8 + (q >> 1) * 16;
                if (r < NSRC0) atomicAdd(&el[r * NH1 + h], pe[q]);
                if (wanter && r < NDST0) atomicAdd(&er[r * NH1 + h], pr[q]);
            }
        }
    }
}

// ---------------- fp32 -> fp16 conversion (chunked) + el/er zero-fill in chunk 0 ----------------
// processes float4 indices [i0, i1); zero-fill only runs for chunk containing low indices
__global__ void convA(const float* __restrict__ f, __half* __restrict__ o,
                      float* __restrict__ el, float* __restrict__ er,
                      size_t i0, size_t i1)
{
    size_t i = i0 + (size_t)blockIdx.x * blockDim.x + threadIdx.x;
    if (i < NSRC0 * NH1) el[i] = 0.f;
    if (i < NDST0 * NH1) er[i] = 0.f;
    if (i >= i1) return;
    float4 v;
    if (i < (size_t)NSRC0 * HD1 / 4) v = ((const float4*)f)[i];
    else v = make_float4(0.f, 0.f, 0.f, 0.f);
    ((__half2*)o)[2 * i] = __floats2half2_rn(v.x, v.y);
    ((__half2*)o)[2 * i + 1] = __floats2half2_rn(v.z, v.w);
}
// transpose W1 [K,N] -> Bt [N,K] fp16, 32x32 smem tiles (coalesced both sides)
__global__ __launch_bounds__(256) void convB(const float* __restrict__ W, __half* __restrict__ o)
{
    __shared__ float tile[32][33];
    int kb = blockIdx.x * 32, nb = blockIdx.y * 32;
    int tx = threadIdx.x & 31, ty = threadIdx.x >> 5;   // 32 x 8
#pragma unroll
    for (int r = 0; r < 32; r += 8)
        tile[ty + r][tx] = W[(size_t)(kb + ty + r) * HD1 + nb + tx];
    __syncthreads();
#pragma unroll
    for (int r = 0; r < 32; r += 8)
        o[(size_t)(nb + ty + r) * HD1 + kb + tx] = __float2half_rn(tile[tx][ty + r]);
}

// ---------------- layer-2 SGEMM + fused scores2 ----------------
__global__ __launch_bounds__(256) void gemm2(
    const float* __restrict__ A, const float* __restrict__ B,
    float* __restrict__ C, int M,
    const float* __restrict__ al2, const float* __restrict__ ar2,
    float* __restrict__ el, float* __restrict__ er)
{
    const int BM = 128, BN = 128, BK = 8, TM = 8, TN = 8;
    const int K = ND1, N = ND2;
    __shared__ float As[BK][BM];
    __shared__ float Bs[BK][BN];

    int tid = threadIdx.x;
    int tx = tid & 15, ty = tid >> 4;
    int rowBase = blockIdx.y * BM;
    int aRow = tid >> 1, aCol = (tid & 1) * 4;
    int bRow = tid >> 5, bCol = (tid & 31) * 4;

    float acc[TM][TN];
#pragma unroll
    for (int i = 0; i < TM; i++)
#pragma unroll
        for (int j = 0; j < TN; j++) acc[i][j] = 0.f;

    for (int kt = 0; kt < K; kt += BK) {
        int gr = rowBase + aRow;
        float4 av = (gr < M) ? *(const float4*)(A + (size_t)gr * K + kt + aCol)
                             : make_float4(0.f, 0.f, 0.f, 0.f);
        As[aCol + 0][aRow] = av.x; As[aCol + 1][aRow] = av.y;
        As[aCol + 2][aRow] = av.z; As[aCol + 3][aRow] = av.w;
        float4 bv = *(const float4*)(B + (size_t)(kt + bRow) * N + bCol);
        *(float4*)&Bs[bRow][bCol] = bv;
        __syncthreads();
#pragma unroll
        for (int k = 0; k < BK; k++) {
            float ar_[TM], br_[TN];
#pragma unroll
            for (int i = 0; i < TM; i++) ar_[i] = As[k][ty * TM + i];
#pragma unroll
            for (int j = 0; j < TN; j++) br_[j] = Bs[k][tx * TN + j];
#pragma unroll
            for (int i = 0; i < TM; i++)
#pragma unroll
                for (int j = 0; j < TN; j++) acc[i][j] += ar_[i] * br_[j];
        }
        __syncthreads();
    }
#pragma unroll
    for (int i = 0; i < TM; i++) {
        int gr = rowBase + ty * TM + i;
        if (gr < M) {
            float* cp = C + (size_t)gr * N + tx * TN;
#pragma unroll
            for (int j = 0; j < TN; j += 4)
                *(float4*)(cp + j) = make_float4(acc[i][j], acc[i][j + 1], acc[i][j + 2], acc[i][j + 3]);
        }
    }

    // ---- fused scores2: half-warp (16 tx lanes) covers all 128 cols of 8 rows ----
    {
        float a2[TN], r2[TN];
#pragma unroll
        for (int j = 0; j < TN; j++) {
            a2[j] = __ldg(al2 + tx * TN + j);
            r2[j] = __ldg(ar2 + tx * TN + j);
        }
        float pl[TM], pr_[TM];
#pragma unroll
        for (int i = 0; i < TM; i++) {
            float sl = 0.f, sr = 0.f;
#pragma unroll
            for (int j = 0; j < TN; j++) { sl += acc[i][j] * a2[j]; sr += acc[i][j] * r2[j]; }
            pl[i] = sl; pr_[i] = sr;
        }
#pragma unroll
        for (int o = 1; o < 16; o <<= 1)
#pragma unroll
            for (int i = 0; i < TM; i++) {
                pl[i] += __shfl_xor_sync(0xffffffffu, pl[i], o);
                pr_[i] += __shfl_xor_sync(0xffffffffu, pr_[i], o);
            }
        if (tx == 0) {
#pragma unroll
            for (int i = 0; i < TM; i++) {
                int gr = rowBase + ty * TM + i;
                if (gr < M) el[gr] = pl[i];
                if (gr < NDST1) er[gr] = pr_[i];
            }
        }
    }
}

// ---------------- CSR build (both layers merged) ----------------
__global__ void count_edges2(const int* __restrict__ dst0, int ne0, int* __restrict__ cnt0,
                             const int* __restrict__ dst1, int ne1, int* __restrict__ cnt1) {
    int e = blockIdx.x * blockDim.x + threadIdx.x;
    if (e < ne0) atomicAdd(&cnt0[dst0[e]], 1);
    if (e < ne1) atomicAdd(&cnt1[dst1[e]], 1);
}
__global__ __launch_bounds__(1024) void scan_excl2(
    const int* __restrict__ cntA, int* __restrict__ offA, int nA,
    const int* __restrict__ cntB, int* __restrict__ offB, int nB)
{
    const int* cnt = (blockIdx.x == 0) ? cntA : cntB;
    int* off = (blockIdx.x == 0) ? offA : offB;
    int n = (blockIdx.x == 0) ? nA : nB;
    __shared__ int s[1024];
    __shared__ int stot;
    int t = threadIdx.x;
    int chunk = (n + 1023) >> 10;
    int b = t * chunk;
    int e = b + chunk; if (e > n) e = n;
    int loc = 0;
    for (int i = b; i < e; i++) loc += cnt[i];
    s[t] = loc;
    __syncthreads();
    if (t == 0) {
        int run = 0;
        for (int i = 0; i < 1024; i++) { int x = s[i]; s[i] = run; run += x; }
        stot = run;
    }
    __syncthreads();
    int run = s[t];
    for (int i = b; i < e; i++) { off[i] = run; run += cnt[i]; }
    if (t == 0) off[n] = stot;
}
__global__ void scatter_edges2(
    const int* __restrict__ src0, const int* __restrict__ dst0, int ne0,
    const int* __restrict__ off0, int* __restrict__ cur0, int* __restrict__ esrc0,
    const int* __restrict__ src1, const int* __restrict__ dst1, int ne1,
    const int* __restrict__ off1, int* __restrict__ cur1, int* __restrict__ esrc1) {
    int e = blockIdx.x * blockDim.x + threadIdx.x;
    if (e < ne0) {
        int d = dst0[e];
        esrc0[off0[d] + atomicAdd(&cur0[d], 1)] = src0[e];
    }
    if (e < ne1) {
        int d = dst1[e];
        esrc1[off1[d] + atomicAdd(&cur1[d], 1)] = src1[e];
    }
}

// ---------------- layer-1 aggregate: head-per-warp vectorized gather ----------------
__global__ __launch_bounds__(256) void aggregate1(
    const __half* __restrict__ h1, const float* __restrict__ el,
    const float* __restrict__ er, const float* __restrict__ b1,
    const int* __restrict__ off, const int* __restrict__ esrc,
    float* __restrict__ hm)
{
    int d = blockIdx.x, t = threadIdx.x;
    int wid = t >> 5, lane = t & 31;
    __shared__ float s_e[256][NH1];
    __shared__ int   s_src[256];
    __shared__ float s_out[NH1][ND1];

    int s0 = off[d], s1 = off[d + 1];
    float ssum = 0.f;
    float acc[8];
#pragma unroll
    for (int k = 0; k < 8; k++) acc[k] = 0.f;
    float erh[NH1];
#pragma unroll
    for (int h = 0; h < NH1; h++) erh[h] = er[d * NH1 + h];

    for (int base = s0; base < s1; base += 256) {
        int cn = s1 - base; if (cn > 256) cn = 256;
        if (t < cn) {
            int s = esrc[base + t];
            s_src[t] = s;
#pragma unroll
            for (int h = 0; h < NH1; h++) {
                float x = el[s * NH1 + h] + erh[h];
                x = (x > 0.f) ? x : 0.2f * x;   // leaky_relu(0.2)
                s_e[t][h] = __expf(x);          // shift-free: |x| small, no overflow
            }
        }
        __syncthreads();

#pragma unroll 4
        for (int j = 0; j < cn; j++) {
            float w = s_e[j][wid];
            ssum += w;
            const uint4 v = *(const uint4*)(h1 + (size_t)s_src[j] * HD1 + wid * ND1 + lane * 8);
            float2 f0 = __half22float2(*(const __half2*)&v.x);
            float2 f1 = __half22float2(*(((const __half2*)&v.x) + 1));
            float2 f2 = __half22float2(*(const __half2*)&v.z);
            float2 f3 = __half22float2(*(((const __half2*)&v.z) + 1));
            acc[0] += w * f0.x; acc[1] += w * f0.y;
            acc[2] += w * f1.x; acc[3] += w * f1.y;
            acc[4] += w * f2.x; acc[5] += w * f2.y;
            acc[6] += w * f3.x; acc[7] += w * f3.y;
        }
        __syncthreads();
    }

    float inv = (ssum > 0.f) ? 1.f / ssum : 0.f;
#pragma unroll
    for (int k = 0; k < 8; k++) {
        float o = acc[k] * inv + b1[wid * ND1 + lane * 8 + k];
        s_out[wid][lane * 8 + k] = fmaxf(o, 0.f);
    }
    __syncthreads();

    float sum = 0.f;
#pragma unroll
    for (int h = 0; h < NH1; h++) sum += s_out[h][t];
    hm[(size_t)d * ND1 + t] = sum * 0.125f;
}

// ---------------- layer-2 aggregate (shift-free softmax) ----------------
__global__ __launch_bounds__(128) void aggregate2(
    const float* __restrict__ h2, const float* __restrict__ el,
    const float* __restrict__ er, const float* __restrict__ b2,
    const int* __restrict__ off, const int* __restrict__ esrc,
    float* __restrict__ out)
{
    int d = blockIdx.x, t = threadIdx.x;
    __shared__ float s_e[128];
    __shared__ int   s_src[128];

    int s0 = off[d], s1 = off[d + 1];
    float ssum = 0.f, acc = 0.f;
    float erh = er[d];

    for (int base = s0; base < s1; base += 128) {
        int cn = s1 - base; if (cn > 128) cn = 128;
        if (t < cn) {
            int s = esrc[base + t];
            s_src[t] = s;
            float x = el[s] + erh;
            x = (x > 0.f) ? x : 0.2f * x;
            s_e[t] = __expf(x);
        }
        __syncthreads();

#pragma unroll 4
        for (int j = 0; j < cn; j++) {
            float w = s_e[j];
            ssum += w;
            acc += w * h2[(size_t)s_src[j] * ND2 + t];
        }
        __syncthreads();
    }

    float o = (ssum > 0.f) ? acc / ssum : 0.f;
    out[(size_t)d * ND2 + t] = o + b2[t];
}

// ---------------- launch ----------------
extern "C" void kernel_launch(void* const* d_in, const int* in_sizes, int n_in,
                              void* d_out, int out_size)
{
    const float* feat = (const float*)d_in[0];
    const float* W1   = (const float*)d_in[1];
    const float* al1  = (const float*)d_in[2];
    const float* ar1  = (const float*)d_in[3];
    const float* b1   = (const float*)d_in[4];
    const float* W2   = (const float*)d_in[5];
    const float* al2  = (const float*)d_in[6];
    const float* ar2  = (const float*)d_in[7];
    const float* b2   = (const float*)d_in[8];
    const int* src0 = (const int*)d_in[9];
    const int* dst0 = (const int*)d_in[10];
    const int* src1 = (const int*)d_in[11];
    const int* dst1 = (const int*)d_in[12];
    float* out = (float*)d_out;

    int e0 = in_sizes[9];
    int e1 = in_sizes[11];
    int emax = (e0 > e1) ? e0 : e1;

    __half *Ahp, *Bhp, *h1p;
    float *hmp, *h2p, *el1p, *er1p, *el2p, *er2p;
    int *off1p, *cnt1p, *esrc1p, *off2p, *cnt2p, *esrc2p;
    cudaGetSymbolAddress((void**)&Ahp, g_Ah);
    cudaGetSymbolAddress((void**)&Bhp, g_Bh);
    cudaGetSymbolAddress((void**)&h1p, g_h1);
    cudaGetSymbolAddress((void**)&hmp, g_hm);
    cudaGetSymbolAddress((void**)&h2p, g_h2);
    cudaGetSymbolAddress((void**)&el1p, g_el1);
    cudaGetSymbolAddress((void**)&er1p, g_er1);
    cudaGetSymbolAddress((void**)&el2p, g_el2);
    cudaGetSymbolAddress((void**)&er2p, g_er2);
    cudaGetSymbolAddress((void**)&off1p, g_off1);
    cudaGetSymbolAddress((void**)&cnt1p, g_cnt1);
    cudaGetSymbolAddress((void**)&esrc1p, g_esrc1);
    cudaGetSymbolAddress((void**)&off2p, g_off2);
    cudaGetSymbolAddress((void**)&cnt2p, g_cnt2);
    cudaGetSymbolAddress((void**)&esrc2p, g_esrc2);

    const int SMEM_GEMM = NSTAGE * STG;  // 96 KB
    cudaFuncSetAttribute(gemm_mma, cudaFuncAttributeMaxDynamicSharedMemorySize, SMEM_GEMM);

    // streams/events (host resources only)
    cudaStream_t s2, s3;
    cudaStreamCreateWithFlags(&s2, cudaStreamNonBlocking);
    cudaStreamCreateWithFlags(&s3, cudaStreamNonBlocking);
    cudaEvent_t evFork, evA0, evA1, evCSR, evG1;
    cudaEventCreateWithFlags(&evFork, cudaEventDisableTiming);
    cudaEventCreateWithFlags(&evA0, cudaEventDisableTiming);
    cudaEventCreateWithFlags(&evA1, cudaEventDisableTiming);
    cudaEventCreateWithFlags(&evCSR, cudaEventDisableTiming);
    cudaEventCreateWithFlags(&evG1, cudaEventDisableTiming);

    cudaEventRecord(evFork, 0);
    cudaStreamWaitEvent(s2, evFork, 0);

    // ---- side stream s2: convB, convA chunks, CSR ----
    const size_t N4 = (size_t)MPAD * HD1 / 4;
    const size_t SPLIT = (size_t)YCH0 * GBM * (HD1 / 4);   // float4 idx boundary of row band 0

    convB<<<dim3(HD1 / 32, HD1 / 32), 256, 0, s2>>>(W1, Bhp);
    convA<<<(unsigned)((SPLIT + 255) / 256), 256, 0, s2>>>(feat, Ahp, el1p, er1p, 0, SPLIT);
    cudaEventRecord(evA0, s2);
    convA<<<(unsigned)((N4 - SPLIT + 255) / 256), 256, 0, s2>>>(feat, Ahp, el1p, er1p, SPLIT, N4);
    cudaEventRecord(evA1, s2);

    cudaMemsetAsync(cnt1p, 0, NDST0 * sizeof(int), s2);
    cudaMemsetAsync(cnt2p, 0, NDST1 * sizeof(int), s2);
    count_edges2<<<(emax + 255) / 256, 256, 0, s2>>>(dst0, e0, cnt1p, dst1, e1, cnt2p);
    scan_excl2<<<2, 1024, 0, s2>>>(cnt1p, off1p, NDST0, cnt2p, off2p, NDST1);
    cudaMemsetAsync(cnt1p, 0, NDST0 * sizeof(int), s2);
    cudaMemsetAsync(cnt2p, 0, NDST1 * sizeof(int), s2);
    scatter_edges2<<<(emax + 255) / 256, 256, 0, s2>>>(src0, dst0, e0, off1p, cnt1p, esrc1p,
                                                       src1, dst1, e1, off2p, cnt2p, esrc2p);
    cudaEventRecord(evCSR, s2);

    // ---- GEMM chunk 0 (main stream): rows [0, YCH0*128) ----
    cudaStreamWaitEvent(0, evA0, 0);
    {
        dim3 grid(HD1 / GBN, YCH0);
        gemm_mma<<<grid, 256, SMEM_GEMM>>>(Ahp, Bhp, h1p, NSRC0, 0,
                                           al1, ar1, el1p, er1p);
    }
    // ---- GEMM chunk 1 (stream s3): rows [YCH0*128, MPAD) ----
    cudaStreamWaitEvent(s3, evA1, 0);
    {
        dim3 grid(HD1 / GBN, YCH1);
        gemm_mma<<<grid, 256, SMEM_GEMM, s3>>>(Ahp, Bhp, h1p, NSRC0, YCH0,
                                               al1, ar1, el1p, er1p);
    }
    cudaEventRecord(evG1, s3);

    // ---- join: aggregate1 needs both GEMM chunks + CSR ----
    cudaStreamWaitEvent(0, evG1, 0);
    cudaStreamWaitEvent(0, evCSR, 0);
    aggregate1<<<NDST0, 256>>>(h1p, el1p, er1p, b1, off1p, esrc1p, hmp);

    {
        dim3 grid(1, (NDST0 + 127) / 128);
        gemm2<<<grid, 256>>>(hmp, W2, h2p, NDST0, al2, ar2, el2p, er2p);
    }

    aggregate2<<<NDST1, 128>>>(h2p, el2p, er2p, b2, off2p, esrc2p, out);

    cudaEventDestroy(evFork);
    cudaEventDestroy(evA0);
    cudaEventDestroy(evA1);
    cudaEventDestroy(evCSR);
    cudaEventDestroy(evG1);
    cudaStreamDestroy(s2);
    cudaStreamDestroy(s3);
}